// round 4
// baseline (speedup 1.0000x reference)
#include <cuda_runtime.h>
#include <mma.h>

using namespace nvcuda;

// Problem constants
constexpr int B_   = 8;
constexpr int H_   = 8;
constexpr int S_   = 1024;
constexpr int DK_  = 64;
constexpr int EMB_ = 512;
constexpr int HD_  = 512;   // H*DK
constexpr int BH_  = 64;    // B*H
constexpr int SD_  = S_ * DK_;   // 65536

// Scratch (device globals: allocation-free rule)
__device__ float gQ[BH_ * S_ * DK_];   // 16 MB, pre-scaled by 1/8
__device__ float gK[BH_ * S_ * DK_];
__device__ float gV[BH_ * S_ * DK_];
__device__ float gO[BH_ * S_ * DK_];
__device__ float gS[(size_t)BH_ * S_ * S_];  // 256 MB: scores -> weights

__device__ __forceinline__ float tf32r(float x) { return wmma::__float_to_tf32(x); }

// ---------------------------------------------------------------------------
// Kernel 1: QKV projection. 3xTF32 split for near-fp32 accuracy.
// C[m,n] = X[m,:512] @ W[:512,n] + bias[n], scaled; written to [B,H,S,DK].
// Block tile 64x64, BK=32, 8 warps (4x2), warp tile 16x32.
// ---------------------------------------------------------------------------
__global__ __launch_bounds__(256)
void proj_kernel(const float* __restrict__ X, const float* __restrict__ W,
                 const float* __restrict__ bias, int which, float scale)
{
    __shared__ float smem[64 * 40 * 2 + 32 * 72 * 2];  // Ahi, Alo, Bhi, Blo
    float* sAhi = smem;
    float* sAlo = smem + 64 * 40;
    float* sBhi = smem + 64 * 40 * 2;
    float* sBlo = smem + 64 * 40 * 2 + 32 * 72;

    const int tid = threadIdx.x;
    const int wid = tid >> 5;
    const int warpRow = wid >> 1;   // 0..3
    const int warpCol = wid & 1;    // 0..1
    const int m0 = blockIdx.y * 64;
    const int n0 = blockIdx.x * 64;

    float* outp = (which == 0) ? gQ : (which == 1) ? gK : gV;

    wmma::fragment<wmma::accumulator, 16, 16, 8, float> acc[2];
    wmma::fill_fragment(acc[0], 0.0f);
    wmma::fill_fragment(acc[1], 0.0f);

    for (int kt = 0; kt < EMB_ / 32; kt++) {
        const int k0 = kt * 32;
        // A tile 64x32
        #pragma unroll
        for (int i = 0; i < 2; i++) {
            int fi = tid + i * 256;
            int row = fi >> 3, c4 = (fi & 7) * 4;
            float4 v = *(const float4*)(X + (m0 + row) * EMB_ + k0 + c4);
            float4 hi, lo;
            hi.x = tf32r(v.x); lo.x = tf32r(v.x - hi.x);
            hi.y = tf32r(v.y); lo.y = tf32r(v.y - hi.y);
            hi.z = tf32r(v.z); lo.z = tf32r(v.z - hi.z);
            hi.w = tf32r(v.w); lo.w = tf32r(v.w - hi.w);
            *(float4*)(sAhi + row * 40 + c4) = hi;
            *(float4*)(sAlo + row * 40 + c4) = lo;
        }
        // B tile 32x64
        #pragma unroll
        for (int i = 0; i < 2; i++) {
            int fi = tid + i * 256;
            int row = fi >> 4, c4 = (fi & 15) * 4;
            float4 v = *(const float4*)(W + (k0 + row) * HD_ + n0 + c4);
            float4 hi, lo;
            hi.x = tf32r(v.x); lo.x = tf32r(v.x - hi.x);
            hi.y = tf32r(v.y); lo.y = tf32r(v.y - hi.y);
            hi.z = tf32r(v.z); lo.z = tf32r(v.z - hi.z);
            hi.w = tf32r(v.w); lo.w = tf32r(v.w - hi.w);
            *(float4*)(sBhi + row * 72 + c4) = hi;
            *(float4*)(sBlo + row * 72 + c4) = lo;
        }
        __syncthreads();
        #pragma unroll
        for (int kk = 0; kk < 4; kk++) {
            wmma::fragment<wmma::matrix_a, 16, 16, 8, wmma::precision::tf32, wmma::row_major> ah, al;
            wmma::load_matrix_sync(ah, sAhi + (warpRow * 16) * 40 + kk * 8, 40);
            wmma::load_matrix_sync(al, sAlo + (warpRow * 16) * 40 + kk * 8, 40);
            #pragma unroll
            for (int j = 0; j < 2; j++) {
                wmma::fragment<wmma::matrix_b, 16, 16, 8, wmma::precision::tf32, wmma::row_major> bh, bl;
                wmma::load_matrix_sync(bh, sBhi + (kk * 8) * 72 + warpCol * 32 + j * 16, 72);
                wmma::load_matrix_sync(bl, sBlo + (kk * 8) * 72 + warpCol * 32 + j * 16, 72);
                wmma::mma_sync(acc[j], ah, bh, acc[j]);
                wmma::mma_sync(acc[j], ah, bl, acc[j]);
                wmma::mma_sync(acc[j], al, bh, acc[j]);
            }
        }
        __syncthreads();
    }

    // Epilogue: stage, add bias, scale, scatter to [B,H,S,DK]
    float* stage = smem;  // 64x68 fits
    #pragma unroll
    for (int j = 0; j < 2; j++)
        wmma::store_matrix_sync(stage + (warpRow * 16) * 68 + warpCol * 32 + j * 16,
                                acc[j], 68, wmma::mem_row_major);
    __syncthreads();
    #pragma unroll
    for (int i = 0; i < 16; i++) {
        int idx = tid + i * 256;
        int r = idx >> 6, c = idx & 63;
        int m = m0 + r, n = n0 + c;
        float v = (stage[r * 68 + c] + bias[n]) * scale;
        int b = m >> 10, s = m & 1023, h = n >> 6, d = n & 63;
        outp[((b * H_ + h) << 16) + (s << 6) + d] = v;
    }
}

// ---------------------------------------------------------------------------
// Kernel 2: edge-key bias + attn_bias -> gS.
// Per q: [64(bh) x 64(d)] @ Ek[q][64(d) x 1024(k)], N-chunk 256.
// gS[bh,q,k] = sum_d gQ[bh,q,d]*Ek[q,k,d] + attn_bias[b,q,k]
// ---------------------------------------------------------------------------
__global__ __launch_bounds__(256)
void edge_bias_kernel(const float* __restrict__ Ek, const float* __restrict__ abias)
{
    extern __shared__ float dsm[];
    float* sA = dsm;                 // 64 x 72
    float* sB = dsm + 64 * 72;       // 64 x 264  (B[d][n]); reused as staging

    const int tid = threadIdx.x;
    const int wid = tid >> 5;
    const int warpRow = wid >> 2;    // 0..1 (32 rows each)
    const int warpCol = wid & 3;     // 0..3 (64 cols each)
    const int q  = blockIdx.y;
    const int n0 = blockIdx.x * 256;

    // A: gQ rows (bh) x 64 d
    #pragma unroll
    for (int i = 0; i < 4; i++) {
        int fi = tid + i * 256;
        int row = fi >> 4, c4 = (fi & 15) * 4;
        float4 v = *(const float4*)(gQ + row * SD_ + q * DK_ + c4);
        v.x = tf32r(v.x); v.y = tf32r(v.y); v.z = tf32r(v.z); v.w = tf32r(v.w);
        *(float4*)(sA + row * 72 + c4) = v;
    }
    // B: Ek[q, n0+n, d] -> sB[d][n]  (transpose stage)
    #pragma unroll
    for (int i = 0; i < 16; i++) {
        int fi = tid + i * 256;
        int n = fi >> 4, c4 = (fi & 15) * 4;
        float4 v = *(const float4*)(Ek + (q * S_ + n0 + n) * DK_ + c4);
        sB[(c4 + 0) * 264 + n] = tf32r(v.x);
        sB[(c4 + 1) * 264 + n] = tf32r(v.y);
        sB[(c4 + 2) * 264 + n] = tf32r(v.z);
        sB[(c4 + 3) * 264 + n] = tf32r(v.w);
    }
    __syncthreads();

    wmma::fragment<wmma::accumulator, 16, 16, 8, float> acc[2][4];
    #pragma unroll
    for (int mi = 0; mi < 2; mi++)
        #pragma unroll
        for (int ni = 0; ni < 4; ni++)
            wmma::fill_fragment(acc[mi][ni], 0.0f);

    #pragma unroll
    for (int kk = 0; kk < 8; kk++) {
        wmma::fragment<wmma::matrix_a, 16, 16, 8, wmma::precision::tf32, wmma::row_major> a[2];
        wmma::load_matrix_sync(a[0], sA + (warpRow * 32 + 0)  * 72 + kk * 8, 72);
        wmma::load_matrix_sync(a[1], sA + (warpRow * 32 + 16) * 72 + kk * 8, 72);
        #pragma unroll
        for (int ni = 0; ni < 4; ni++) {
            wmma::fragment<wmma::matrix_b, 16, 16, 8, wmma::precision::tf32, wmma::row_major> b;
            wmma::load_matrix_sync(b, sB + (kk * 8) * 264 + warpCol * 64 + ni * 16, 264);
            wmma::mma_sync(acc[0][ni], a[0], b, acc[0][ni]);
            wmma::mma_sync(acc[1][ni], a[1], b, acc[1][ni]);
        }
    }
    __syncthreads();

    // stage into sB region, then add attn_bias and write gS
    #pragma unroll
    for (int mi = 0; mi < 2; mi++)
        #pragma unroll
        for (int ni = 0; ni < 4; ni++)
            wmma::store_matrix_sync(sB + (warpRow * 32 + mi * 16) * 264 + warpCol * 64 + ni * 16,
                                    acc[mi][ni], 264, wmma::mem_row_major);
    __syncthreads();
    #pragma unroll
    for (int i = 0; i < 64; i++) {
        int idx = tid + i * 256;
        int r = idx >> 8, c = idx & 255;
        float v = sB[r * 264 + c] + abias[(r >> 3) * (S_ * S_) + q * S_ + n0 + c];
        gS[(r * S_ + q) * S_ + n0 + c] = v;
    }
}

// ---------------------------------------------------------------------------
// Kernel 3: scores = QK^T + gS, then row softmax, weights overwrite gS.
// CTA per (bh, 32-row q-tile). 32x1024 tile kept in smem.
// ---------------------------------------------------------------------------
__global__ __launch_bounds__(256)
void scores_softmax_kernel()
{
    extern __shared__ float dsm[];
    float* sA = dsm;                          // 32 x 72
    float* sB = dsm + 32 * 72;                // 64 x 136  (K^T chunk [d][n])
    float* sT = dsm + 32 * 72 + 64 * 136;     // 32 x 1024

    const int tid = threadIdx.x;
    const int wid = tid >> 5;
    const int lane = tid & 31;
    const int warpRow = wid >> 2;   // 0..1
    const int warpCol = wid & 3;    // 0..3
    const int bh = blockIdx.y;
    const int q0 = blockIdx.x * 32;

    #pragma unroll
    for (int i = 0; i < 2; i++) {
        int fi = tid + i * 256;
        int row = fi >> 4, c4 = (fi & 15) * 4;
        float4 v = *(const float4*)(gQ + bh * SD_ + (q0 + row) * DK_ + c4);
        v.x = tf32r(v.x); v.y = tf32r(v.y); v.z = tf32r(v.z); v.w = tf32r(v.w);
        *(float4*)(sA + row * 72 + c4) = v;
    }
    __syncthreads();

    for (int nc = 0; nc < 8; nc++) {
        const int n0 = nc * 128;
        #pragma unroll
        for (int i = 0; i < 8; i++) {
            int fi = tid + i * 256;
            int n = fi >> 4, c4 = (fi & 15) * 4;
            float4 v = *(const float4*)(gK + bh * SD_ + (n0 + n) * DK_ + c4);
            sB[(c4 + 0) * 136 + n] = tf32r(v.x);
            sB[(c4 + 1) * 136 + n] = tf32r(v.y);
            sB[(c4 + 2) * 136 + n] = tf32r(v.z);
            sB[(c4 + 3) * 136 + n] = tf32r(v.w);
        }
        __syncthreads();

        wmma::fragment<wmma::accumulator, 16, 16, 8, float> acc[2];
        wmma::fill_fragment(acc[0], 0.0f);
        wmma::fill_fragment(acc[1], 0.0f);
        #pragma unroll
        for (int kk = 0; kk < 8; kk++) {
            wmma::fragment<wmma::matrix_a, 16, 16, 8, wmma::precision::tf32, wmma::row_major> a;
            wmma::load_matrix_sync(a, sA + (warpRow * 16) * 72 + kk * 8, 72);
            #pragma unroll
            for (int ni = 0; ni < 2; ni++) {
                wmma::fragment<wmma::matrix_b, 16, 16, 8, wmma::precision::tf32, wmma::row_major> b;
                wmma::load_matrix_sync(b, sB + (kk * 8) * 136 + warpCol * 32 + ni * 16, 136);
                wmma::mma_sync(acc[ni], a, b, acc[ni]);
            }
        }
        #pragma unroll
        for (int ni = 0; ni < 2; ni++)
            wmma::store_matrix_sync(sT + (warpRow * 16) * 1024 + n0 + warpCol * 32 + ni * 16,
                                    acc[ni], 1024, wmma::mem_row_major);
        __syncthreads();
        // add edge+attn bias from gS
        #pragma unroll
        for (int i = 0; i < 16; i++) {
            int idx = tid + i * 256;
            int r = idx >> 7, c = idx & 127;
            sT[r * 1024 + n0 + c] += gS[(bh * S_ + q0 + r) * S_ + n0 + c];
        }
        __syncthreads();
    }

    // row softmax: each warp owns 4 rows
    #pragma unroll
    for (int rr = 0; rr < 4; rr++) {
        int r = wid * 4 + rr;
        float* row = sT + r * 1024;
        float mx = -3.0e38f;
        for (int i = lane; i < 1024; i += 32) mx = fmaxf(mx, row[i]);
        #pragma unroll
        for (int o = 16; o; o >>= 1) mx = fmaxf(mx, __shfl_xor_sync(0xffffffffu, mx, o));
        float sum = 0.0f;
        for (int i = lane; i < 1024; i += 32) {
            float e = expf(row[i] - mx);
            row[i] = e;
            sum += e;
        }
        #pragma unroll
        for (int o = 16; o; o >>= 1) sum += __shfl_xor_sync(0xffffffffu, sum, o);
        float inv = 1.0f / sum;
        float* outr = gS + (bh * S_ + q0 + r) * S_;
        for (int i = lane; i < 1024; i += 32) outr[i] = row[i] * inv;
    }
}

// ---------------------------------------------------------------------------
// Kernel 4: gO = weights @ V, batched over bh. M=1024 (tiles 64), N=64, K=1024.
// ---------------------------------------------------------------------------
__global__ __launch_bounds__(256)
void attnv_kernel()
{
    __shared__ float smem[64 * 40 + 32 * 72];
    float* sA = smem;
    float* sB = smem + 64 * 40;

    const int tid = threadIdx.x;
    const int wid = tid >> 5;
    const int warpRow = wid >> 1;   // 0..3
    const int warpCol = wid & 1;    // 0..1
    const int bh = blockIdx.y;
    const int m0 = blockIdx.x * 64;

    wmma::fragment<wmma::accumulator, 16, 16, 8, float> acc[2];
    wmma::fill_fragment(acc[0], 0.0f);
    wmma::fill_fragment(acc[1], 0.0f);

    for (int kt = 0; kt < 32; kt++) {
        const int k0 = kt * 32;
        #pragma unroll
        for (int i = 0; i < 2; i++) {
            int fi = tid + i * 256;
            int row = fi >> 3, c4 = (fi & 7) * 4;
            float4 v = *(const float4*)(gS + (bh * S_ + m0 + row) * S_ + k0 + c4);
            v.x = tf32r(v.x); v.y = tf32r(v.y); v.z = tf32r(v.z); v.w = tf32r(v.w);
            *(float4*)(sA + row * 40 + c4) = v;
        }
        #pragma unroll
        for (int i = 0; i < 2; i++) {
            int fi = tid + i * 256;
            int row = fi >> 4, c4 = (fi & 15) * 4;
            float4 v = *(const float4*)(gV + bh * SD_ + (k0 + row) * DK_ + c4);
            v.x = tf32r(v.x); v.y = tf32r(v.y); v.z = tf32r(v.z); v.w = tf32r(v.w);
            *(float4*)(sB + row * 72 + c4) = v;
        }
        __syncthreads();
        #pragma unroll
        for (int kk = 0; kk < 4; kk++) {
            wmma::fragment<wmma::matrix_a, 16, 16, 8, wmma::precision::tf32, wmma::row_major> a;
            wmma::load_matrix_sync(a, sA + (warpRow * 16) * 40 + kk * 8, 40);
            #pragma unroll
            for (int j = 0; j < 2; j++) {
                wmma::fragment<wmma::matrix_b, 16, 16, 8, wmma::precision::tf32, wmma::row_major> b;
                wmma::load_matrix_sync(b, sB + (kk * 8) * 72 + warpCol * 32 + j * 16, 72);
                wmma::mma_sync(acc[j], a, b, acc[j]);
            }
        }
        __syncthreads();
    }

    float* stage = smem;
    #pragma unroll
    for (int j = 0; j < 2; j++)
        wmma::store_matrix_sync(stage + (warpRow * 16) * 68 + warpCol * 32 + j * 16,
                                acc[j], 68, wmma::mem_row_major);
    __syncthreads();
    #pragma unroll
    for (int i = 0; i < 16; i++) {
        int idx = tid + i * 256;
        int r = idx >> 6, c = idx & 63;
        gO[bh * SD_ + (m0 + r) * DK_ + c] = stage[r * 68 + c];
    }
}

// ---------------------------------------------------------------------------
// Kernel 5: gO += weights[:,q,:] @ Ev[q]. Per q: M=64(bh), N=64(d), K=1024.
// ---------------------------------------------------------------------------
__global__ __launch_bounds__(256)
void edgev_kernel(const float* __restrict__ Ev)
{
    __shared__ float smem[64 * 40 + 32 * 72];
    float* sA = smem;
    float* sB = smem + 64 * 40;

    const int tid = threadIdx.x;
    const int wid = tid >> 5;
    const int warpRow = wid >> 1;
    const int warpCol = wid & 1;
    const int q = blockIdx.x;

    wmma::fragment<wmma::accumulator, 16, 16, 8, float> acc[2];
    wmma::fill_fragment(acc[0], 0.0f);
    wmma::fill_fragment(acc[1], 0.0f);

    for (int kt = 0; kt < 32; kt++) {
        const int k0 = kt * 32;
        #pragma unroll
        for (int i = 0; i < 2; i++) {
            int fi = tid + i * 256;
            int row = fi >> 3, c4 = (fi & 7) * 4;
            float4 v = *(const float4*)(gS + (row * S_ + q) * S_ + k0 + c4);
            v.x = tf32r(v.x); v.y = tf32r(v.y); v.z = tf32r(v.z); v.w = tf32r(v.w);
            *(float4*)(sA + row * 40 + c4) = v;
        }
        #pragma unroll
        for (int i = 0; i < 2; i++) {
            int fi = tid + i * 256;
            int row = fi >> 4, c4 = (fi & 15) * 4;
            float4 v = *(const float4*)(Ev + (q * S_ + k0 + row) * DK_ + c4);
            v.x = tf32r(v.x); v.y = tf32r(v.y); v.z = tf32r(v.z); v.w = tf32r(v.w);
            *(float4*)(sB + row * 72 + c4) = v;
        }
        __syncthreads();
        #pragma unroll
        for (int kk = 0; kk < 4; kk++) {
            wmma::fragment<wmma::matrix_a, 16, 16, 8, wmma::precision::tf32, wmma::row_major> a;
            wmma::load_matrix_sync(a, sA + (warpRow * 16) * 40 + kk * 8, 40);
            #pragma unroll
            for (int j = 0; j < 2; j++) {
                wmma::fragment<wmma::matrix_b, 16, 16, 8, wmma::precision::tf32, wmma::row_major> b;
                wmma::load_matrix_sync(b, sB + (kk * 8) * 72 + warpCol * 32 + j * 16, 72);
                wmma::mma_sync(acc[j], a, b, acc[j]);
            }
        }
        __syncthreads();
    }

    float* stage = smem;
    #pragma unroll
    for (int j = 0; j < 2; j++)
        wmma::store_matrix_sync(stage + (warpRow * 16) * 68 + warpCol * 32 + j * 16,
                                acc[j], 68, wmma::mem_row_major);
    __syncthreads();
    #pragma unroll
    for (int i = 0; i < 16; i++) {
        int idx = tid + i * 256;
        int r = idx >> 6, c = idx & 63;     // r = bh, c = d
        gO[(r * S_ + q) * DK_ + c] += stage[r * 68 + c];
    }
}

// ---------------------------------------------------------------------------
// Kernel 6: out = concat_heads(gO) @ Wp + bp. 3xTF32. A gathered from [B,H,S,DK].
// ---------------------------------------------------------------------------
__global__ __launch_bounds__(256)
void final_kernel(const float* __restrict__ Wp, const float* __restrict__ bp,
                  float* __restrict__ out)
{
    __shared__ float smem[64 * 40 * 2 + 32 * 72 * 2];
    float* sAhi = smem;
    float* sAlo = smem + 64 * 40;
    float* sBhi = smem + 64 * 40 * 2;
    float* sBlo = smem + 64 * 40 * 2 + 32 * 72;

    const int tid = threadIdx.x;
    const int wid = tid >> 5;
    const int warpRow = wid >> 1;
    const int warpCol = wid & 1;
    const int m0 = blockIdx.y * 64;
    const int n0 = blockIdx.x * 64;
    const int bb = m0 >> 10;          // whole tile in one b
    const int sBase = m0 & 1023;

    wmma::fragment<wmma::accumulator, 16, 16, 8, float> acc[2];
    wmma::fill_fragment(acc[0], 0.0f);
    wmma::fill_fragment(acc[1], 0.0f);

    for (int kt = 0; kt < HD_ / 32; kt++) {
        const int k0 = kt * 32;
        const int h = k0 >> 6, d0 = k0 & 63;
        const float* Abase = gO + ((bb * H_ + h) << 16) + d0;
        #pragma unroll
        for (int i = 0; i < 2; i++) {
            int fi = tid + i * 256;
            int row = fi >> 3, c4 = (fi & 7) * 4;
            float4 v = *(const float4*)(Abase + (sBase + row) * DK_ + c4);
            float4 hi, lo;
            hi.x = tf32r(v.x); lo.x = tf32r(v.x - hi.x);
            hi.y = tf32r(v.y); lo.y = tf32r(v.y - hi.y);
            hi.z = tf32r(v.z); lo.z = tf32r(v.z - hi.z);
            hi.w = tf32r(v.w); lo.w = tf32r(v.w - hi.w);
            *(float4*)(sAhi + row * 40 + c4) = hi;
            *(float4*)(sAlo + row * 40 + c4) = lo;
        }
        #pragma unroll
        for (int i = 0; i < 2; i++) {
            int fi = tid + i * 256;
            int row = fi >> 4, c4 = (fi & 15) * 4;
            float4 v = *(const float4*)(Wp + (k0 + row) * HD_ + n0 + c4);
            float4 hi, lo;
            hi.x = tf32r(v.x); lo.x = tf32r(v.x - hi.x);
            hi.y = tf32r(v.y); lo.y = tf32r(v.y - hi.y);
            hi.z = tf32r(v.z); lo.z = tf32r(v.z - hi.z);
            hi.w = tf32r(v.w); lo.w = tf32r(v.w - hi.w);
            *(float4*)(sBhi + row * 72 + c4) = hi;
            *(float4*)(sBlo + row * 72 + c4) = lo;
        }
        __syncthreads();
        #pragma unroll
        for (int kk = 0; kk < 4; kk++) {
            wmma::fragment<wmma::matrix_a, 16, 16, 8, wmma::precision::tf32, wmma::row_major> ah, al;
            wmma::load_matrix_sync(ah, sAhi + (warpRow * 16) * 40 + kk * 8, 40);
            wmma::load_matrix_sync(al, sAlo + (warpRow * 16) * 40 + kk * 8, 40);
            #pragma unroll
            for (int j = 0; j < 2; j++) {
                wmma::fragment<wmma::matrix_b, 16, 16, 8, wmma::precision::tf32, wmma::row_major> bh, bl;
                wmma::load_matrix_sync(bh, sBhi + (kk * 8) * 72 + warpCol * 32 + j * 16, 72);
                wmma::load_matrix_sync(bl, sBlo + (kk * 8) * 72 + warpCol * 32 + j * 16, 72);
                wmma::mma_sync(acc[j], ah, bh, acc[j]);
                wmma::mma_sync(acc[j], ah, bl, acc[j]);
                wmma::mma_sync(acc[j], al, bh, acc[j]);
            }
        }
        __syncthreads();
    }

    float* stage = smem;
    #pragma unroll
    for (int j = 0; j < 2; j++)
        wmma::store_matrix_sync(stage + (warpRow * 16) * 68 + warpCol * 32 + j * 16,
                                acc[j], 68, wmma::mem_row_major);
    __syncthreads();
    #pragma unroll
    for (int i = 0; i < 16; i++) {
        int idx = tid + i * 256;
        int r = idx >> 6, c = idx & 63;
        out[(m0 + r) * HD_ + n0 + c] = stage[r * 68 + c] + bp[n0 + c];
    }
}

// ---------------------------------------------------------------------------
extern "C" void kernel_launch(void* const* d_in, const int* in_sizes, int n_in,
                              void* d_out, int out_size)
{
    const float* queries = (const float*)d_in[0];
    const float* keys    = (const float*)d_in[1];
    const float* values  = (const float*)d_in[2];
    const float* Ek      = (const float*)d_in[3];
    const float* Ev      = (const float*)d_in[4];
    const float* abias   = (const float*)d_in[5];
    const float* Wq = (const float*)d_in[6];
    const float* bq = (const float*)d_in[7];
    const float* Wk = (const float*)d_in[8];
    const float* bk = (const float*)d_in[9];
    const float* Wv = (const float*)d_in[10];
    const float* bv = (const float*)d_in[11];
    const float* Wp = (const float*)d_in[12];
    const float* bp = (const float*)d_in[13];
    float* out = (float*)d_out;

    const int SMEM_EB = (64 * 72 + 64 * 264) * (int)sizeof(float);            // 86016
    const int SMEM_SS = (32 * 72 + 64 * 136 + 32 * 1024) * (int)sizeof(float); // 175104
    cudaFuncSetAttribute(edge_bias_kernel, cudaFuncAttributeMaxDynamicSharedMemorySize, SMEM_EB);
    cudaFuncSetAttribute(scores_softmax_kernel, cudaFuncAttributeMaxDynamicSharedMemorySize, SMEM_SS);

    dim3 blk(256);
    proj_kernel<<<dim3(8, 128), blk>>>(queries, Wq, bq, 0, 0.125f);
    proj_kernel<<<dim3(8, 128), blk>>>(keys,    Wk, bk, 1, 1.0f);
    proj_kernel<<<dim3(8, 128), blk>>>(values,  Wv, bv, 2, 1.0f);

    edge_bias_kernel<<<dim3(4, 1024), blk, SMEM_EB>>>(Ek, abias);
    scores_softmax_kernel<<<dim3(32, 64), blk, SMEM_SS>>>();

    attnv_kernel<<<dim3(16, 64), blk>>>();
    edgev_kernel<<<1024, blk>>>(Ev);

    final_kernel<<<dim3(8, 128), blk>>>(Wp, bp, out);
}

// round 5
// speedup vs baseline: 1.0526x; 1.0526x over previous
#include <cuda_runtime.h>
#include <mma.h>

using namespace nvcuda;

// Problem constants
constexpr int B_   = 8;
constexpr int H_   = 8;
constexpr int S_   = 1024;
constexpr int DK_  = 64;
constexpr int EMB_ = 512;
constexpr int HD_  = 512;   // H*DK
constexpr int BH_  = 64;    // B*H
constexpr int SD_  = S_ * DK_;   // 65536

// Scratch (device globals: allocation-free rule)
__device__ float gQ[BH_ * S_ * DK_];   // 16 MB, pre-scaled by 1/8
__device__ float gK[BH_ * S_ * DK_];
__device__ float gV[BH_ * S_ * DK_];
__device__ float gO[BH_ * S_ * DK_];
__device__ float gS[(size_t)BH_ * S_ * S_];  // 256 MB: score-bias -> weights (tf32-rounded)

__device__ __forceinline__ float tf32r(float x) { return wmma::__float_to_tf32(x); }

// ---------------------------------------------------------------------------
// Kernel 1: QKV projection. 3xTF32 split for near-fp32 accuracy.
// ---------------------------------------------------------------------------
__global__ __launch_bounds__(256)
void proj_kernel(const float* __restrict__ X, const float* __restrict__ W,
                 const float* __restrict__ bias, int which, float scale)
{
    __shared__ float smem[64 * 40 * 2 + 32 * 72 * 2];  // Ahi, Alo, Bhi, Blo
    float* sAhi = smem;
    float* sAlo = smem + 64 * 40;
    float* sBhi = smem + 64 * 40 * 2;
    float* sBlo = smem + 64 * 40 * 2 + 32 * 72;

    const int tid = threadIdx.x;
    const int wid = tid >> 5;
    const int warpRow = wid >> 1;   // 0..3
    const int warpCol = wid & 1;    // 0..1
    const int m0 = blockIdx.y * 64;
    const int n0 = blockIdx.x * 64;

    float* outp = (which == 0) ? gQ : (which == 1) ? gK : gV;

    wmma::fragment<wmma::accumulator, 16, 16, 8, float> acc[2];
    wmma::fill_fragment(acc[0], 0.0f);
    wmma::fill_fragment(acc[1], 0.0f);

    for (int kt = 0; kt < EMB_ / 32; kt++) {
        const int k0 = kt * 32;
        #pragma unroll
        for (int i = 0; i < 2; i++) {
            int fi = tid + i * 256;
            int row = fi >> 3, c4 = (fi & 7) * 4;
            float4 v = *(const float4*)(X + (m0 + row) * EMB_ + k0 + c4);
            float4 hi, lo;
            hi.x = tf32r(v.x); lo.x = tf32r(v.x - hi.x);
            hi.y = tf32r(v.y); lo.y = tf32r(v.y - hi.y);
            hi.z = tf32r(v.z); lo.z = tf32r(v.z - hi.z);
            hi.w = tf32r(v.w); lo.w = tf32r(v.w - hi.w);
            *(float4*)(sAhi + row * 40 + c4) = hi;
            *(float4*)(sAlo + row * 40 + c4) = lo;
        }
        #pragma unroll
        for (int i = 0; i < 2; i++) {
            int fi = tid + i * 256;
            int row = fi >> 4, c4 = (fi & 15) * 4;
            float4 v = *(const float4*)(W + (k0 + row) * HD_ + n0 + c4);
            float4 hi, lo;
            hi.x = tf32r(v.x); lo.x = tf32r(v.x - hi.x);
            hi.y = tf32r(v.y); lo.y = tf32r(v.y - hi.y);
            hi.z = tf32r(v.z); lo.z = tf32r(v.z - hi.z);
            hi.w = tf32r(v.w); lo.w = tf32r(v.w - hi.w);
            *(float4*)(sBhi + row * 72 + c4) = hi;
            *(float4*)(sBlo + row * 72 + c4) = lo;
        }
        __syncthreads();
        #pragma unroll
        for (int kk = 0; kk < 4; kk++) {
            wmma::fragment<wmma::matrix_a, 16, 16, 8, wmma::precision::tf32, wmma::row_major> ah, al;
            wmma::load_matrix_sync(ah, sAhi + (warpRow * 16) * 40 + kk * 8, 40);
            wmma::load_matrix_sync(al, sAlo + (warpRow * 16) * 40 + kk * 8, 40);
            #pragma unroll
            for (int j = 0; j < 2; j++) {
                wmma::fragment<wmma::matrix_b, 16, 16, 8, wmma::precision::tf32, wmma::row_major> bh, bl;
                wmma::load_matrix_sync(bh, sBhi + (kk * 8) * 72 + warpCol * 32 + j * 16, 72);
                wmma::load_matrix_sync(bl, sBlo + (kk * 8) * 72 + warpCol * 32 + j * 16, 72);
                wmma::mma_sync(acc[j], ah, bh, acc[j]);
                wmma::mma_sync(acc[j], ah, bl, acc[j]);
                wmma::mma_sync(acc[j], al, bh, acc[j]);
            }
        }
        __syncthreads();
    }

    float* stage = smem;  // 64x68
    #pragma unroll
    for (int j = 0; j < 2; j++)
        wmma::store_matrix_sync(stage + (warpRow * 16) * 68 + warpCol * 32 + j * 16,
                                acc[j], 68, wmma::mem_row_major);
    __syncthreads();
    #pragma unroll
    for (int i = 0; i < 16; i++) {
        int idx = tid + i * 256;
        int r = idx >> 6, c = idx & 63;
        int m = m0 + r, n = n0 + c;
        float v = (stage[r * 68 + c] + bias[n]) * scale;
        int b = m >> 10, s = m & 1023, h = n >> 6, d = n & 63;
        outp[((b * H_ + h) << 16) + (s << 6) + d] = v;
    }
}

// ---------------------------------------------------------------------------
// Kernel 2: edge-key bias + attn_bias -> gS.  (col_major B: no transpose)
// Per q: [64(bh) x 64(d)] @ Ek[q]^T -> [64 x 256(k-chunk)]
// ---------------------------------------------------------------------------
__global__ __launch_bounds__(256, 2)
void edge_bias_kernel(const float* __restrict__ Ek, const float* __restrict__ abias)
{
    extern __shared__ float dsm[];
    float* sA = dsm;                 // 64 x 72 (gQ slice, rounded)
    float* sB = dsm + 64 * 72;       // 256 x 68 (Ek tile as stored: row=kpos, col=d); reused as staging

    const int tid = threadIdx.x;
    const int wid = tid >> 5;
    const int warpRow = wid >> 2;    // 0..1
    const int warpCol = wid & 3;     // 0..3
    const int q  = blockIdx.y;
    const int n0 = blockIdx.x * 256;

    #pragma unroll
    for (int i = 0; i < 4; i++) {
        int fi = tid + i * 256;
        int row = fi >> 4, c4 = (fi & 15) * 4;
        float4 v = *(const float4*)(gQ + row * SD_ + q * DK_ + c4);
        v.x = tf32r(v.x); v.y = tf32r(v.y); v.z = tf32r(v.z); v.w = tf32r(v.w);
        *(float4*)(sA + row * 72 + c4) = v;
    }
    #pragma unroll
    for (int i = 0; i < 16; i++) {
        int fi = tid + i * 256;
        int n = fi >> 4, c4 = (fi & 15) * 4;
        float4 v = *(const float4*)(Ek + (q * S_ + n0 + n) * DK_ + c4);
        v.x = tf32r(v.x); v.y = tf32r(v.y); v.z = tf32r(v.z); v.w = tf32r(v.w);
        *(float4*)(sB + n * 68 + c4) = v;
    }
    __syncthreads();

    wmma::fragment<wmma::accumulator, 16, 16, 8, float> acc[2][4];
    #pragma unroll
    for (int mi = 0; mi < 2; mi++)
        #pragma unroll
        for (int ni = 0; ni < 4; ni++)
            wmma::fill_fragment(acc[mi][ni], 0.0f);

    #pragma unroll
    for (int kk = 0; kk < 8; kk++) {
        wmma::fragment<wmma::matrix_a, 16, 16, 8, wmma::precision::tf32, wmma::row_major> a[2];
        wmma::load_matrix_sync(a[0], sA + (warpRow * 32 + 0)  * 72 + kk * 8, 72);
        wmma::load_matrix_sync(a[1], sA + (warpRow * 32 + 16) * 72 + kk * 8, 72);
        #pragma unroll
        for (int ni = 0; ni < 4; ni++) {
            wmma::fragment<wmma::matrix_b, 16, 16, 8, wmma::precision::tf32, wmma::col_major> b;
            wmma::load_matrix_sync(b, sB + (warpCol * 64 + ni * 16) * 68 + kk * 8, 68);
            wmma::mma_sync(acc[0][ni], a[0], b, acc[0][ni]);
            wmma::mma_sync(acc[1][ni], a[1], b, acc[1][ni]);
        }
    }
    __syncthreads();

    #pragma unroll
    for (int mi = 0; mi < 2; mi++)
        #pragma unroll
        for (int ni = 0; ni < 4; ni++)
            wmma::store_matrix_sync(sB + (warpRow * 32 + mi * 16) * 264 + warpCol * 64 + ni * 16,
                                    acc[mi][ni], 264, wmma::mem_row_major);
    __syncthreads();
    #pragma unroll
    for (int i = 0; i < 64; i++) {
        int idx = tid + i * 256;
        int r = idx >> 8, c = idx & 255;
        float v = sB[r * 264 + c] + abias[(r >> 3) * (S_ * S_) + q * S_ + n0 + c];
        gS[(r * S_ + q) * S_ + n0 + c] = v;
    }
}

// ---------------------------------------------------------------------------
// Kernel 3 (FUSED): scores = QK^T + gS -> softmax -> weights (to gS, rounded)
//                   -> out = weights @ V (to gO).  CTA per (bh, 32-q-rows).
// ---------------------------------------------------------------------------
__global__ __launch_bounds__(256)
void fused_attn_kernel()
{
    extern __shared__ float dsm[];
    float* sQ  = dsm;                            // 32 x 72
    float* sKV = dsm + 32 * 72;                  // 128 x 68 (K chunk as stored; later V chunk 64x68)
    float* sT  = dsm + 32 * 72 + 128 * 68;       // 32 x 1024

    const int tid = threadIdx.x;
    const int wid = tid >> 5;
    const int lane = tid & 31;
    const int bh = blockIdx.y;
    const int q0 = blockIdx.x * 32;

    #pragma unroll
    for (int i = 0; i < 2; i++) {
        int fi = tid + i * 256;
        int row = fi >> 4, c4 = (fi & 15) * 4;
        float4 v = *(const float4*)(gQ + bh * SD_ + (q0 + row) * DK_ + c4);
        v.x = tf32r(v.x); v.y = tf32r(v.y); v.z = tf32r(v.z); v.w = tf32r(v.w);
        *(float4*)(sQ + row * 72 + c4) = v;
    }

    // ---- Phase A: scores chunks of 128 keys ----
    {
        const int wr = wid >> 2;   // 0..1
        const int wc = wid & 3;    // 0..3
        for (int nc = 0; nc < 8; nc++) {
            const int n0 = nc * 128;
            __syncthreads();
            #pragma unroll
            for (int i = 0; i < 8; i++) {
                int fi = tid + i * 256;
                int n = fi >> 4, c4 = (fi & 15) * 4;
                float4 v = *(const float4*)(gK + bh * SD_ + (n0 + n) * DK_ + c4);
                v.x = tf32r(v.x); v.y = tf32r(v.y); v.z = tf32r(v.z); v.w = tf32r(v.w);
                *(float4*)(sKV + n * 68 + c4) = v;
            }
            __syncthreads();

            wmma::fragment<wmma::accumulator, 16, 16, 8, float> acc[2];
            #pragma unroll
            for (int ni = 0; ni < 2; ni++)   // init acc from gS (edge+attn bias)
                wmma::load_matrix_sync(acc[ni],
                    gS + (bh * S_ + q0 + wr * 16) * S_ + n0 + wc * 32 + ni * 16,
                    S_, wmma::mem_row_major);
            #pragma unroll
            for (int kk = 0; kk < 8; kk++) {
                wmma::fragment<wmma::matrix_a, 16, 16, 8, wmma::precision::tf32, wmma::row_major> a;
                wmma::load_matrix_sync(a, sQ + (wr * 16) * 72 + kk * 8, 72);
                #pragma unroll
                for (int ni = 0; ni < 2; ni++) {
                    wmma::fragment<wmma::matrix_b, 16, 16, 8, wmma::precision::tf32, wmma::col_major> b;
                    wmma::load_matrix_sync(b, sKV + (wc * 32 + ni * 16) * 68 + kk * 8, 68);
                    wmma::mma_sync(acc[ni], a, b, acc[ni]);
                }
            }
            #pragma unroll
            for (int ni = 0; ni < 2; ni++)
                wmma::store_matrix_sync(sT + (wr * 16) * 1024 + n0 + wc * 32 + ni * 16,
                                        acc[ni], 1024, wmma::mem_row_major);
        }
    }
    __syncthreads();

    // ---- Phase B: row softmax; rounded weights to sT and gS ----
    #pragma unroll
    for (int rr = 0; rr < 4; rr++) {
        int r = wid * 4 + rr;
        float* row = sT + r * 1024;
        float mx = -3.0e38f;
        for (int i = lane; i < 1024; i += 32) mx = fmaxf(mx, row[i]);
        #pragma unroll
        for (int o = 16; o; o >>= 1) mx = fmaxf(mx, __shfl_xor_sync(0xffffffffu, mx, o));
        float sum = 0.0f;
        for (int i = lane; i < 1024; i += 32) {
            float e = expf(row[i] - mx);
            row[i] = e;
            sum += e;
        }
        #pragma unroll
        for (int o = 16; o; o >>= 1) sum += __shfl_xor_sync(0xffffffffu, sum, o);
        float inv = 1.0f / sum;
        float* outr = gS + (bh * S_ + q0 + r) * S_;
        for (int i = lane; i < 1024; i += 32) {
            float w = tf32r(row[i] * inv);
            row[i] = w;
            outr[i] = w;
        }
    }

    // ---- Phase C: out = weights @ V ----
    {
        const int wr = wid >> 2;   // 0..1 (M)
        const int wc = wid & 3;    // 0..3 (N, 16 cols each)
        wmma::fragment<wmma::accumulator, 16, 16, 8, float> o;
        wmma::fill_fragment(o, 0.0f);
        float* sV = sKV;
        for (int kt = 0; kt < 16; kt++) {
            const int k0 = kt * 64;
            __syncthreads();
            #pragma unroll
            for (int i = 0; i < 4; i++) {
                int fi = tid + i * 256;
                int row = fi >> 4, c4 = (fi & 15) * 4;
                float4 v = *(const float4*)(gV + bh * SD_ + (k0 + row) * DK_ + c4);
                v.x = tf32r(v.x); v.y = tf32r(v.y); v.z = tf32r(v.z); v.w = tf32r(v.w);
                *(float4*)(sV + row * 68 + c4) = v;
            }
            __syncthreads();
            #pragma unroll
            for (int kk = 0; kk < 8; kk++) {
                wmma::fragment<wmma::matrix_a, 16, 16, 8, wmma::precision::tf32, wmma::row_major> a;
                wmma::load_matrix_sync(a, sT + (wr * 16) * 1024 + k0 + kk * 8, 1024);
                wmma::fragment<wmma::matrix_b, 16, 16, 8, wmma::precision::tf32, wmma::row_major> b;
                wmma::load_matrix_sync(b, sV + (kk * 8) * 68 + wc * 16, 68);
                wmma::mma_sync(o, a, b, o);
            }
        }
        wmma::store_matrix_sync(gO + bh * SD_ + (q0 + wr * 16) * DK_ + wc * 16,
                                o, DK_, wmma::mem_row_major);
    }
}

// ---------------------------------------------------------------------------
// Kernel 4: gO += weights[:,q,:] @ Ev[q]. Per q: M=64(bh), N=64(d), K=1024.
// Accumulators loaded/stored directly from/to gO. K-chunk 64.
// ---------------------------------------------------------------------------
__global__ __launch_bounds__(256, 2)
void edgev_kernel(const float* __restrict__ Ev)
{
    __shared__ float sA[64 * 68];
    __shared__ float sB[64 * 68];

    const int tid = threadIdx.x;
    const int wid = tid >> 5;
    const int warpRow = wid >> 1;   // 0..3
    const int warpCol = wid & 1;    // 0..1
    const int q = blockIdx.x;

    wmma::fragment<wmma::accumulator, 16, 16, 8, float> acc[2];
    #pragma unroll
    for (int j = 0; j < 2; j++)
        wmma::load_matrix_sync(acc[j],
            gO + (size_t)(warpRow * 16) * SD_ + q * DK_ + warpCol * 32 + j * 16,
            SD_, wmma::mem_row_major);

    for (int kt = 0; kt < 16; kt++) {
        const int k0 = kt * 64;
        __syncthreads();
        #pragma unroll
        for (int i = 0; i < 4; i++) {
            int fi = tid + i * 256;
            int row = fi >> 4, c4 = (fi & 15) * 4;
            // weights already tf32-rounded in gS
            float4 v = *(const float4*)(gS + (size_t)(row * S_ + q) * S_ + k0 + c4);
            *(float4*)(sA + row * 68 + c4) = v;
        }
        #pragma unroll
        for (int i = 0; i < 4; i++) {
            int fi = tid + i * 256;
            int row = fi >> 4, c4 = (fi & 15) * 4;
            float4 v = *(const float4*)(Ev + ((size_t)q * S_ + k0 + row) * DK_ + c4);
            v.x = tf32r(v.x); v.y = tf32r(v.y); v.z = tf32r(v.z); v.w = tf32r(v.w);
            *(float4*)(sB + row * 68 + c4) = v;
        }
        __syncthreads();
        #pragma unroll
        for (int kk = 0; kk < 8; kk++) {
            wmma::fragment<wmma::matrix_a, 16, 16, 8, wmma::precision::tf32, wmma::row_major> a;
            wmma::load_matrix_sync(a, sA + (warpRow * 16) * 68 + kk * 8, 68);
            #pragma unroll
            for (int j = 0; j < 2; j++) {
                wmma::fragment<wmma::matrix_b, 16, 16, 8, wmma::precision::tf32, wmma::row_major> b;
                wmma::load_matrix_sync(b, sB + (kk * 8) * 68 + warpCol * 32 + j * 16, 68);
                wmma::mma_sync(acc[j], a, b, acc[j]);
            }
        }
    }

    #pragma unroll
    for (int j = 0; j < 2; j++)
        wmma::store_matrix_sync(
            gO + (size_t)(warpRow * 16) * SD_ + q * DK_ + warpCol * 32 + j * 16,
            acc[j], SD_, wmma::mem_row_major);
}

// ---------------------------------------------------------------------------
// Kernel 5: out = concat_heads(gO) @ Wp + bp. 3xTF32.
// ---------------------------------------------------------------------------
__global__ __launch_bounds__(256)
void final_kernel(const float* __restrict__ Wp, const float* __restrict__ bp,
                  float* __restrict__ out)
{
    __shared__ float smem[64 * 40 * 2 + 32 * 72 * 2];
    float* sAhi = smem;
    float* sAlo = smem + 64 * 40;
    float* sBhi = smem + 64 * 40 * 2;
    float* sBlo = smem + 64 * 40 * 2 + 32 * 72;

    const int tid = threadIdx.x;
    const int wid = tid >> 5;
    const int warpRow = wid >> 1;
    const int warpCol = wid & 1;
    const int m0 = blockIdx.y * 64;
    const int n0 = blockIdx.x * 64;
    const int bb = m0 >> 10;
    const int sBase = m0 & 1023;

    wmma::fragment<wmma::accumulator, 16, 16, 8, float> acc[2];
    wmma::fill_fragment(acc[0], 0.0f);
    wmma::fill_fragment(acc[1], 0.0f);

    for (int kt = 0; kt < HD_ / 32; kt++) {
        const int k0 = kt * 32;
        const int h = k0 >> 6, d0 = k0 & 63;
        const float* Abase = gO + ((bb * H_ + h) << 16) + d0;
        #pragma unroll
        for (int i = 0; i < 2; i++) {
            int fi = tid + i * 256;
            int row = fi >> 3, c4 = (fi & 7) * 4;
            float4 v = *(const float4*)(Abase + (sBase + row) * DK_ + c4);
            float4 hi, lo;
            hi.x = tf32r(v.x); lo.x = tf32r(v.x - hi.x);
            hi.y = tf32r(v.y); lo.y = tf32r(v.y - hi.y);
            hi.z = tf32r(v.z); lo.z = tf32r(v.z - hi.z);
            hi.w = tf32r(v.w); lo.w = tf32r(v.w - hi.w);
            *(float4*)(sAhi + row * 40 + c4) = hi;
            *(float4*)(sAlo + row * 40 + c4) = lo;
        }
        #pragma unroll
        for (int i = 0; i < 2; i++) {
            int fi = tid + i * 256;
            int row = fi >> 4, c4 = (fi & 15) * 4;
            float4 v = *(const float4*)(Wp + (k0 + row) * HD_ + n0 + c4);
            float4 hi, lo;
            hi.x = tf32r(v.x); lo.x = tf32r(v.x - hi.x);
            hi.y = tf32r(v.y); lo.y = tf32r(v.y - hi.y);
            hi.z = tf32r(v.z); lo.z = tf32r(v.z - hi.z);
            hi.w = tf32r(v.w); lo.w = tf32r(v.w - hi.w);
            *(float4*)(sBhi + row * 72 + c4) = hi;
            *(float4*)(sBlo + row * 72 + c4) = lo;
        }
        __syncthreads();
        #pragma unroll
        for (int kk = 0; kk < 4; kk++) {
            wmma::fragment<wmma::matrix_a, 16, 16, 8, wmma::precision::tf32, wmma::row_major> ah, al;
            wmma::load_matrix_sync(ah, sAhi + (warpRow * 16) * 40 + kk * 8, 40);
            wmma::load_matrix_sync(al, sAlo + (warpRow * 16) * 40 + kk * 8, 40);
            #pragma unroll
            for (int j = 0; j < 2; j++) {
                wmma::fragment<wmma::matrix_b, 16, 16, 8, wmma::precision::tf32, wmma::row_major> bh, bl;
                wmma::load_matrix_sync(bh, sBhi + (kk * 8) * 72 + warpCol * 32 + j * 16, 72);
                wmma::load_matrix_sync(bl, sBlo + (kk * 8) * 72 + warpCol * 32 + j * 16, 72);
                wmma::mma_sync(acc[j], ah, bh, acc[j]);
                wmma::mma_sync(acc[j], ah, bl, acc[j]);
                wmma::mma_sync(acc[j], al, bh, acc[j]);
            }
        }
        __syncthreads();
    }

    float* stage = smem;
    #pragma unroll
    for (int j = 0; j < 2; j++)
        wmma::store_matrix_sync(stage + (warpRow * 16) * 68 + warpCol * 32 + j * 16,
                                acc[j], 68, wmma::mem_row_major);
    __syncthreads();
    #pragma unroll
    for (int i = 0; i < 16; i++) {
        int idx = tid + i * 256;
        int r = idx >> 6, c = idx & 63;
        out[(m0 + r) * HD_ + n0 + c] = stage[r * 68 + c] + bp[n0 + c];
    }
}

// ---------------------------------------------------------------------------
extern "C" void kernel_launch(void* const* d_in, const int* in_sizes, int n_in,
                              void* d_out, int out_size)
{
    const float* queries = (const float*)d_in[0];
    const float* keys    = (const float*)d_in[1];
    const float* values  = (const float*)d_in[2];
    const float* Ek      = (const float*)d_in[3];
    const float* Ev      = (const float*)d_in[4];
    const float* abias   = (const float*)d_in[5];
    const float* Wq = (const float*)d_in[6];
    const float* bq = (const float*)d_in[7];
    const float* Wk = (const float*)d_in[8];
    const float* bk = (const float*)d_in[9];
    const float* Wv = (const float*)d_in[10];
    const float* bv = (const float*)d_in[11];
    const float* Wp = (const float*)d_in[12];
    const float* bp = (const float*)d_in[13];
    float* out = (float*)d_out;

    const int SMEM_EB = (64 * 72 + 256 * 68) * (int)sizeof(float);              // 88064
    const int SMEM_FA = (32 * 72 + 128 * 68 + 32 * 1024) * (int)sizeof(float);  // 175104
    cudaFuncSetAttribute(edge_bias_kernel, cudaFuncAttributeMaxDynamicSharedMemorySize, SMEM_EB);
    cudaFuncSetAttribute(fused_attn_kernel, cudaFuncAttributeMaxDynamicSharedMemorySize, SMEM_FA);

    dim3 blk(256);
    proj_kernel<<<dim3(8, 128), blk>>>(queries, Wq, bq, 0, 0.125f);
    proj_kernel<<<dim3(8, 128), blk>>>(keys,    Wk, bk, 1, 1.0f);
    proj_kernel<<<dim3(8, 128), blk>>>(values,  Wv, bv, 2, 1.0f);

    edge_bias_kernel<<<dim3(4, 1024), blk, SMEM_EB>>>(Ek, abias);
    fused_attn_kernel<<<dim3(32, 64), blk, SMEM_FA>>>();
    edgev_kernel<<<1024, blk>>>(Ev);

    final_kernel<<<dim3(8, 128), blk>>>(Wp, bp, out);
}

// round 6
// speedup vs baseline: 1.3876x; 1.3183x over previous
#include <cuda_runtime.h>
#include <cuda_bf16.h>
#include <mma.h>

using namespace nvcuda;

constexpr int B_   = 8;
constexpr int H_   = 8;
constexpr int S_   = 1024;
constexpr int DK_  = 64;
constexpr int EMB_ = 512;
constexpr int HD_  = 512;   // H*DK
constexpr int BH_  = 64;    // B*H
constexpr int SD_  = S_ * DK_;   // 65536
constexpr int SS_  = S_ * S_;    // 1048576

// Scratch (device globals: allocation-free rule)
__device__ float gQ[BH_ * S_ * DK_];   // tf32-rounded, q pre-scaled by 1/8
__device__ float gK[BH_ * S_ * DK_];   // tf32-rounded
__device__ float gV[BH_ * S_ * DK_];   // tf32-rounded
__device__ float gO[BH_ * S_ * DK_];
__device__ float gS[(size_t)BH_ * S_ * S_];  // 256 MB: score-bias -> weights (tf32)

__device__ __forceinline__ float tf32r(float x) { return wmma::__float_to_tf32(x); }

// ---------------------------------------------------------------------------
// Kernel 1: merged QKV projection, 3xbf16 split. Tile 128x64, k-chunk 32.
// out = tf32_round((X@W + bias) * scale), scattered to [B,H,S,DK].
// ---------------------------------------------------------------------------
__global__ __launch_bounds__(256)
void proj_kernel(const float* __restrict__ Xq, const float* __restrict__ Xk,
                 const float* __restrict__ Xv,
                 const float* __restrict__ Wq, const float* __restrict__ Wk,
                 const float* __restrict__ Wv,
                 const float* __restrict__ bq, const float* __restrict__ bk,
                 const float* __restrict__ bv)
{
    __shared__ float sBias[16 * 72];
    __shared__ __nv_bfloat16 sAhi[128 * 40], sAlo[128 * 40];
    __shared__ __nv_bfloat16 sBhi[32 * 72],  sBlo[32 * 72];

    const int which = blockIdx.z;
    const float* X    = (which == 0) ? Xq : (which == 1) ? Xk : Xv;
    const float* W    = (which == 0) ? Wq : (which == 1) ? Wk : Wv;
    const float* bias = (which == 0) ? bq : (which == 1) ? bk : bv;
    float* outp       = (which == 0) ? gQ : (which == 1) ? gK : gV;
    const float scale = (which == 0) ? 0.125f : 1.0f;

    const int tid = threadIdx.x;
    const int wid = tid >> 5;
    const int warpRow = wid >> 1;   // 0..3 -> 32 rows each
    const int warpCol = wid & 1;    // 0..1 -> 32 cols each
    const int m0 = blockIdx.y * 128;
    const int n0 = blockIdx.x * 64;
    const int bb = m0 >> 10;        // tile fully within one b (128 | 1024)
    const int sBase = m0 & 1023;
    const int h  = n0 >> 6;         // tile fully within one head

    // bias tile (16 identical rows)
    #pragma unroll
    for (int i = 0; i < 4; i++) {
        int idx = tid + i * 256;
        int r = idx >> 6, c = idx & 63;
        sBias[r * 72 + c] = bias[n0 + c];
    }
    __syncthreads();

    wmma::fragment<wmma::accumulator, 16, 16, 16, float> acc[2][2];
    #pragma unroll
    for (int mi = 0; mi < 2; mi++)
        #pragma unroll
        for (int ni = 0; ni < 2; ni++)
            wmma::load_matrix_sync(acc[mi][ni], sBias + warpCol * 32 + ni * 16,
                                   72, wmma::mem_row_major);

    for (int kt = 0; kt < 16; kt++) {
        const int k0 = kt * 32;
        #pragma unroll
        for (int i = 0; i < 4; i++) {
            int fi = tid + i * 256;
            int row = fi >> 3, c4 = (fi & 7) * 4;
            float4 v = *(const float4*)(X + (m0 + row) * EMB_ + k0 + c4);
            __nv_bfloat16 hx = __float2bfloat16(v.x), hy = __float2bfloat16(v.y);
            __nv_bfloat16 hz = __float2bfloat16(v.z), hw = __float2bfloat16(v.w);
            __nv_bfloat162 h01(hx, hy), h23(hz, hw);
            __nv_bfloat162 l01(__float2bfloat16(v.x - __bfloat162float(hx)),
                               __float2bfloat16(v.y - __bfloat162float(hy)));
            __nv_bfloat162 l23(__float2bfloat16(v.z - __bfloat162float(hz)),
                               __float2bfloat16(v.w - __bfloat162float(hw)));
            *(__nv_bfloat162*)&sAhi[row * 40 + c4]     = h01;
            *(__nv_bfloat162*)&sAhi[row * 40 + c4 + 2] = h23;
            *(__nv_bfloat162*)&sAlo[row * 40 + c4]     = l01;
            *(__nv_bfloat162*)&sAlo[row * 40 + c4 + 2] = l23;
        }
        #pragma unroll
        for (int i = 0; i < 2; i++) {
            int fi = tid + i * 256;
            int row = fi >> 4, c4 = (fi & 15) * 4;
            float4 v = *(const float4*)(W + (k0 + row) * HD_ + n0 + c4);
            __nv_bfloat16 hx = __float2bfloat16(v.x), hy = __float2bfloat16(v.y);
            __nv_bfloat16 hz = __float2bfloat16(v.z), hw = __float2bfloat16(v.w);
            __nv_bfloat162 h01(hx, hy), h23(hz, hw);
            __nv_bfloat162 l01(__float2bfloat16(v.x - __bfloat162float(hx)),
                               __float2bfloat16(v.y - __bfloat162float(hy)));
            __nv_bfloat162 l23(__float2bfloat16(v.z - __bfloat162float(hz)),
                               __float2bfloat16(v.w - __bfloat162float(hw)));
            *(__nv_bfloat162*)&sBhi[row * 72 + c4]     = h01;
            *(__nv_bfloat162*)&sBhi[row * 72 + c4 + 2] = h23;
            *(__nv_bfloat162*)&sBlo[row * 72 + c4]     = l01;
            *(__nv_bfloat162*)&sBlo[row * 72 + c4 + 2] = l23;
        }
        __syncthreads();
        #pragma unroll
        for (int kk = 0; kk < 2; kk++) {
            wmma::fragment<wmma::matrix_b, 16, 16, 16, __nv_bfloat16, wmma::row_major> bhf[2], blf[2];
            #pragma unroll
            for (int ni = 0; ni < 2; ni++) {
                wmma::load_matrix_sync(bhf[ni], sBhi + (kk * 16) * 72 + warpCol * 32 + ni * 16, 72);
                wmma::load_matrix_sync(blf[ni], sBlo + (kk * 16) * 72 + warpCol * 32 + ni * 16, 72);
            }
            #pragma unroll
            for (int mi = 0; mi < 2; mi++) {
                wmma::fragment<wmma::matrix_a, 16, 16, 16, __nv_bfloat16, wmma::row_major> ah, al;
                wmma::load_matrix_sync(ah, sAhi + (warpRow * 32 + mi * 16) * 40 + kk * 16, 40);
                wmma::load_matrix_sync(al, sAlo + (warpRow * 32 + mi * 16) * 40 + kk * 16, 40);
                #pragma unroll
                for (int ni = 0; ni < 2; ni++) {
                    wmma::mma_sync(acc[mi][ni], ah, bhf[ni], acc[mi][ni]);
                    wmma::mma_sync(acc[mi][ni], ah, blf[ni], acc[mi][ni]);
                    wmma::mma_sync(acc[mi][ni], al, bhf[ni], acc[mi][ni]);
                }
            }
        }
        __syncthreads();
    }

    float* obase = outp + ((bb * H_ + h) << 16);
    #pragma unroll
    for (int mi = 0; mi < 2; mi++)
        #pragma unroll
        for (int ni = 0; ni < 2; ni++) {
            #pragma unroll
            for (int e = 0; e < acc[mi][ni].num_elements; e++)
                acc[mi][ni].x[e] = tf32r(acc[mi][ni].x[e] * scale);
            wmma::store_matrix_sync(
                obase + (sBase + warpRow * 32 + mi * 16) * DK_ + warpCol * 32 + ni * 16,
                acc[mi][ni], DK_, wmma::mem_row_major);
        }
}

// ---------------------------------------------------------------------------
// Kernel 2: edge-key bias + attn_bias -> gS.  B frags direct from global Ek.
// Per q: [64(bh) x 64(d)] @ Ek[q]^T -> 128-key chunk.
// ---------------------------------------------------------------------------
__global__ __launch_bounds__(256, 4)
void edge_bias_kernel(const float* __restrict__ Ek, const float* __restrict__ abias)
{
    extern __shared__ float dsm[];   // 64x72 (A) aliased with 64x136 staging
    float* sA = dsm;

    const int tid = threadIdx.x;
    const int wid = tid >> 5;
    const int warpRow = wid >> 2;    // 0..1 -> 32 rows
    const int warpCol = wid & 3;     // 0..3 -> 32 cols
    const int q  = blockIdx.y;
    const int n0 = blockIdx.x * 128;

    #pragma unroll
    for (int i = 0; i < 4; i++) {
        int fi = tid + i * 256;
        int row = fi >> 4, c4 = (fi & 15) * 4;
        *(float4*)(sA + row * 72 + c4) = *(const float4*)(gQ + row * SD_ + q * DK_ + c4);
    }
    __syncthreads();

    wmma::fragment<wmma::accumulator, 16, 16, 8, float> acc[2][2];
    #pragma unroll
    for (int mi = 0; mi < 2; mi++)
        #pragma unroll
        for (int ni = 0; ni < 2; ni++)
            wmma::fill_fragment(acc[mi][ni], 0.0f);

    #pragma unroll
    for (int kk = 0; kk < 8; kk++) {
        wmma::fragment<wmma::matrix_a, 16, 16, 8, wmma::precision::tf32, wmma::row_major> a[2];
        wmma::load_matrix_sync(a[0], sA + (warpRow * 32 + 0)  * 72 + kk * 8, 72);
        wmma::load_matrix_sync(a[1], sA + (warpRow * 32 + 16) * 72 + kk * 8, 72);
        #pragma unroll
        for (int ni = 0; ni < 2; ni++) {
            wmma::fragment<wmma::matrix_b, 16, 16, 8, wmma::precision::tf32, wmma::col_major> b;
            wmma::load_matrix_sync(b, Ek + (q * S_ + n0 + warpCol * 32 + ni * 16) * DK_ + kk * 8, DK_);
            wmma::mma_sync(acc[0][ni], a[0], b, acc[0][ni]);
            wmma::mma_sync(acc[1][ni], a[1], b, acc[1][ni]);
        }
    }
    __syncthreads();

    #pragma unroll
    for (int mi = 0; mi < 2; mi++)
        #pragma unroll
        for (int ni = 0; ni < 2; ni++)
            wmma::store_matrix_sync(dsm + (warpRow * 32 + mi * 16) * 136 + warpCol * 32 + ni * 16,
                                    acc[mi][ni], 136, wmma::mem_row_major);
    __syncthreads();
    #pragma unroll
    for (int i = 0; i < 32; i++) {
        int idx = tid + i * 256;
        int r = idx >> 7, c = idx & 127;
        float v = dsm[r * 136 + c] + abias[(r >> 3) * SS_ + q * S_ + n0 + c];
        gS[(r * S_ + q) * S_ + n0 + c] = v;
    }
}

// ---------------------------------------------------------------------------
// Kernel 3 (FUSED): scores = QK^T + gS -> softmax -> weights (gS, tf32)
//                   -> out = W @ V (gO).  CTA per (bh, 32-q-rows).
// K and V fragments loaded directly from global (pre-rounded by proj).
// ---------------------------------------------------------------------------
__global__ __launch_bounds__(256, 1)
void fused_attn_kernel()
{
    extern __shared__ float dsm[];
    float* sQ = dsm;                 // 32 x 72
    float* sT = dsm + 32 * 72;       // 32 x 1024

    const int tid = threadIdx.x;
    const int wid = tid >> 5;
    const int lane = tid & 31;
    const int bh = blockIdx.y;
    const int q0 = blockIdx.x * 32;

    #pragma unroll
    for (int i = 0; i < 2; i++) {
        int fi = tid + i * 256;
        int row = fi >> 4, c4 = (fi & 15) * 4;
        *(float4*)(sQ + row * 72 + c4) =
            *(const float4*)(gQ + bh * SD_ + (q0 + row) * DK_ + c4);
    }
    __syncthreads();

    // ---- Phase A: scores ----
    {
        const int wr = wid >> 2;   // 0..1
        const int wc = wid & 3;    // 0..3 -> 256 cols each
        wmma::fragment<wmma::matrix_a, 16, 16, 8, wmma::precision::tf32, wmma::row_major> a[8];
        #pragma unroll
        for (int kk = 0; kk < 8; kk++)
            wmma::load_matrix_sync(a[kk], sQ + (wr * 16) * 72 + kk * 8, 72);

        const float* Kbase = gK + bh * SD_;
        const float* Sbase = gS + (bh * S_ + q0 + wr * 16) * S_;
        #pragma unroll 2
        for (int nf = 0; nf < 16; nf++) {
            const int nc = wc * 256 + nf * 16;
            wmma::fragment<wmma::accumulator, 16, 16, 8, float> acc;
            wmma::load_matrix_sync(acc, Sbase + nc, S_, wmma::mem_row_major);
            #pragma unroll
            for (int kk = 0; kk < 8; kk++) {
                wmma::fragment<wmma::matrix_b, 16, 16, 8, wmma::precision::tf32, wmma::col_major> b;
                wmma::load_matrix_sync(b, Kbase + nc * DK_ + kk * 8, DK_);
                wmma::mma_sync(acc, a[kk], b, acc);
            }
            wmma::store_matrix_sync(sT + (wr * 16) * 1024 + nc, acc, 1024, wmma::mem_row_major);
        }
    }
    __syncthreads();

    // ---- Phase B: row softmax; tf32-rounded weights to sT and gS ----
    #pragma unroll
    for (int rr = 0; rr < 4; rr++) {
        int r = wid * 4 + rr;
        float* row = sT + r * 1024;
        float mx = -3.0e38f;
        for (int i = lane; i < 1024; i += 32) mx = fmaxf(mx, row[i]);
        #pragma unroll
        for (int o = 16; o; o >>= 1) mx = fmaxf(mx, __shfl_xor_sync(0xffffffffu, mx, o));
        float sum = 0.0f;
        for (int i = lane; i < 1024; i += 32) {
            float e = expf(row[i] - mx);
            row[i] = e;
            sum += e;
        }
        #pragma unroll
        for (int o = 16; o; o >>= 1) sum += __shfl_xor_sync(0xffffffffu, sum, o);
        float inv = 1.0f / sum;
        float* outr = gS + (bh * S_ + q0 + r) * S_;
        for (int i = lane; i < 1024; i += 32) {
            float w = tf32r(row[i] * inv);
            row[i] = w;
            outr[i] = w;
        }
    }
    __syncthreads();

    // ---- Phase C: out = weights @ V (V frags direct from global) ----
    {
        const int wr = wid >> 2;   // 0..1
        const int wc = wid & 3;    // 0..3 -> 16 cols each
        wmma::fragment<wmma::accumulator, 16, 16, 8, float> c0, c1;
        wmma::fill_fragment(c0, 0.0f);
        wmma::fill_fragment(c1, 0.0f);
        const float* Vbase = gV + bh * SD_ + wc * 16;
        const float* Tbase = sT + (wr * 16) * 1024;
        #pragma unroll 4
        for (int k = 0; k < 64; k++) {
            wmma::fragment<wmma::matrix_a, 16, 16, 8, wmma::precision::tf32, wmma::row_major> a0, a1;
            wmma::fragment<wmma::matrix_b, 16, 16, 8, wmma::precision::tf32, wmma::row_major> b0, b1;
            wmma::load_matrix_sync(a0, Tbase + k * 16, 1024);
            wmma::load_matrix_sync(b0, Vbase + (k * 16) * DK_, DK_);
            wmma::mma_sync(c0, a0, b0, c0);
            wmma::load_matrix_sync(a1, Tbase + k * 16 + 8, 1024);
            wmma::load_matrix_sync(b1, Vbase + (k * 16 + 8) * DK_, DK_);
            wmma::mma_sync(c1, a1, b1, c1);
        }
        #pragma unroll
        for (int e = 0; e < c0.num_elements; e++) c0.x[e] += c1.x[e];
        wmma::store_matrix_sync(gO + bh * SD_ + (q0 + wr * 16) * DK_ + wc * 16,
                                c0, DK_, wmma::mem_row_major);
    }
}

// ---------------------------------------------------------------------------
// Kernel 4: gO += weights[:,q,:] @ Ev[q]. No smem, all fragment loads global.
// ---------------------------------------------------------------------------
__global__ __launch_bounds__(256, 4)
void edgev_kernel(const float* __restrict__ Ev)
{
    const int tid = threadIdx.x;
    const int wid = tid >> 5;
    const int warpRow = wid >> 1;   // 0..3 -> bh rows 16 each
    const int warpCol = wid & 1;    // 0..1 -> 32 cols
    const int q = blockIdx.x;

    wmma::fragment<wmma::accumulator, 16, 16, 8, float> acc[2];
    #pragma unroll
    for (int j = 0; j < 2; j++)
        wmma::load_matrix_sync(acc[j],
            gO + (size_t)(warpRow * 16) * SD_ + q * DK_ + warpCol * 32 + j * 16,
            SD_, wmma::mem_row_major);

    const float* Abase = gS + (size_t)(warpRow * 16) * SS_ + (size_t)q * S_;
    const float* Bbase = Ev + (size_t)q * S_ * DK_ + warpCol * 32;
    #pragma unroll 2
    for (int k = 0; k < 128; k++) {
        wmma::fragment<wmma::matrix_a, 16, 16, 8, wmma::precision::tf32, wmma::row_major> a;
        wmma::load_matrix_sync(a, Abase + k * 8, SS_);
        #pragma unroll
        for (int j = 0; j < 2; j++) {
            wmma::fragment<wmma::matrix_b, 16, 16, 8, wmma::precision::tf32, wmma::row_major> b;
            wmma::load_matrix_sync(b, Bbase + (k * 8) * DK_ + j * 16, DK_);
            wmma::mma_sync(acc[j], a, b, acc[j]);
        }
    }

    #pragma unroll
    for (int j = 0; j < 2; j++)
        wmma::store_matrix_sync(
            gO + (size_t)(warpRow * 16) * SD_ + q * DK_ + warpCol * 32 + j * 16,
            acc[j], SD_, wmma::mem_row_major);
}

// ---------------------------------------------------------------------------
// Kernel 5: out = concat_heads(gO) @ Wp + bp. 3xbf16 split, tile 128x64.
// ---------------------------------------------------------------------------
__global__ __launch_bounds__(256)
void final_kernel(const float* __restrict__ Wp, const float* __restrict__ bp,
                  float* __restrict__ out)
{
    __shared__ float sBias[16 * 72];
    __shared__ __nv_bfloat16 sAhi[128 * 40], sAlo[128 * 40];
    __shared__ __nv_bfloat16 sBhi[32 * 72],  sBlo[32 * 72];

    const int tid = threadIdx.x;
    const int wid = tid >> 5;
    const int warpRow = wid >> 1;
    const int warpCol = wid & 1;
    const int m0 = blockIdx.y * 128;
    const int n0 = blockIdx.x * 64;
    const int bb = m0 >> 10;
    const int sBase = m0 & 1023;

    #pragma unroll
    for (int i = 0; i < 4; i++) {
        int idx = tid + i * 256;
        int r = idx >> 6, c = idx & 63;
        sBias[r * 72 + c] = bp[n0 + c];
    }
    __syncthreads();

    wmma::fragment<wmma::accumulator, 16, 16, 16, float> acc[2][2];
    #pragma unroll
    for (int mi = 0; mi < 2; mi++)
        #pragma unroll
        for (int ni = 0; ni < 2; ni++)
            wmma::load_matrix_sync(acc[mi][ni], sBias + warpCol * 32 + ni * 16,
                                   72, wmma::mem_row_major);

    for (int kt = 0; kt < 16; kt++) {
        const int k0 = kt * 32;
        const int h = k0 >> 6, d0 = k0 & 63;
        const float* Abase = gO + ((bb * H_ + h) << 16) + d0;
        #pragma unroll
        for (int i = 0; i < 4; i++) {
            int fi = tid + i * 256;
            int row = fi >> 3, c4 = (fi & 7) * 4;
            float4 v = *(const float4*)(Abase + (sBase + row) * DK_ + c4);
            __nv_bfloat16 hx = __float2bfloat16(v.x), hy = __float2bfloat16(v.y);
            __nv_bfloat16 hz = __float2bfloat16(v.z), hw = __float2bfloat16(v.w);
            __nv_bfloat162 h01(hx, hy), h23(hz, hw);
            __nv_bfloat162 l01(__float2bfloat16(v.x - __bfloat162float(hx)),
                               __float2bfloat16(v.y - __bfloat162float(hy)));
            __nv_bfloat162 l23(__float2bfloat16(v.z - __bfloat162float(hz)),
                               __float2bfloat16(v.w - __bfloat162float(hw)));
            *(__nv_bfloat162*)&sAhi[row * 40 + c4]     = h01;
            *(__nv_bfloat162*)&sAhi[row * 40 + c4 + 2] = h23;
            *(__nv_bfloat162*)&sAlo[row * 40 + c4]     = l01;
            *(__nv_bfloat162*)&sAlo[row * 40 + c4 + 2] = l23;
        }
        #pragma unroll
        for (int i = 0; i < 2; i++) {
            int fi = tid + i * 256;
            int row = fi >> 4, c4 = (fi & 15) * 4;
            float4 v = *(const float4*)(Wp + (k0 + row) * HD_ + n0 + c4);
            __nv_bfloat16 hx = __float2bfloat16(v.x), hy = __float2bfloat16(v.y);
            __nv_bfloat16 hz = __float2bfloat16(v.z), hw = __float2bfloat16(v.w);
            __nv_bfloat162 h01(hx, hy), h23(hz, hw);
            __nv_bfloat162 l01(__float2bfloat16(v.x - __bfloat162float(hx)),
                               __float2bfloat16(v.y - __bfloat162float(hy)));
            __nv_bfloat162 l23(__float2bfloat16(v.z - __bfloat162float(hz)),
                               __float2bfloat16(v.w - __bfloat162float(hw)));
            *(__nv_bfloat162*)&sBhi[row * 72 + c4]     = h01;
            *(__nv_bfloat162*)&sBhi[row * 72 + c4 + 2] = h23;
            *(__nv_bfloat162*)&sBlo[row * 72 + c4]     = l01;
            *(__nv_bfloat162*)&sBlo[row * 72 + c4 + 2] = l23;
        }
        __syncthreads();
        #pragma unroll
        for (int kk = 0; kk < 2; kk++) {
            wmma::fragment<wmma::matrix_b, 16, 16, 16, __nv_bfloat16, wmma::row_major> bhf[2], blf[2];
            #pragma unroll
            for (int ni = 0; ni < 2; ni++) {
                wmma::load_matrix_sync(bhf[ni], sBhi + (kk * 16) * 72 + warpCol * 32 + ni * 16, 72);
                wmma::load_matrix_sync(blf[ni], sBlo + (kk * 16) * 72 + warpCol * 32 + ni * 16, 72);
            }
            #pragma unroll
            for (int mi = 0; mi < 2; mi++) {
                wmma::fragment<wmma::matrix_a, 16, 16, 16, __nv_bfloat16, wmma::row_major> ah, al;
                wmma::load_matrix_sync(ah, sAhi + (warpRow * 32 + mi * 16) * 40 + kk * 16, 40);
                wmma::load_matrix_sync(al, sAlo + (warpRow * 32 + mi * 16) * 40 + kk * 16, 40);
                #pragma unroll
                for (int ni = 0; ni < 2; ni++) {
                    wmma::mma_sync(acc[mi][ni], ah, bhf[ni], acc[mi][ni]);
                    wmma::mma_sync(acc[mi][ni], ah, blf[ni], acc[mi][ni]);
                    wmma::mma_sync(acc[mi][ni], al, bhf[ni], acc[mi][ni]);
                }
            }
        }
        __syncthreads();
    }

    #pragma unroll
    for (int mi = 0; mi < 2; mi++)
        #pragma unroll
        for (int ni = 0; ni < 2; ni++)
            wmma::store_matrix_sync(
                out + (m0 + warpRow * 32 + mi * 16) * HD_ + n0 + warpCol * 32 + ni * 16,
                acc[mi][ni], HD_, wmma::mem_row_major);
}

// ---------------------------------------------------------------------------
extern "C" void kernel_launch(void* const* d_in, const int* in_sizes, int n_in,
                              void* d_out, int out_size)
{
    const float* queries = (const float*)d_in[0];
    const float* keys    = (const float*)d_in[1];
    const float* values  = (const float*)d_in[2];
    const float* Ek      = (const float*)d_in[3];
    const float* Ev      = (const float*)d_in[4];
    const float* abias   = (const float*)d_in[5];
    const float* Wq = (const float*)d_in[6];
    const float* bq = (const float*)d_in[7];
    const float* Wk = (const float*)d_in[8];
    const float* bk = (const float*)d_in[9];
    const float* Wv = (const float*)d_in[10];
    const float* bv = (const float*)d_in[11];
    const float* Wp = (const float*)d_in[12];
    const float* bp = (const float*)d_in[13];
    float* out = (float*)d_out;

    const int SMEM_EB = 64 * 136 * (int)sizeof(float);                 // 34816
    const int SMEM_FA = (32 * 72 + 32 * 1024) * (int)sizeof(float);    // 140288
    cudaFuncSetAttribute(fused_attn_kernel, cudaFuncAttributeMaxDynamicSharedMemorySize, SMEM_FA);

    dim3 blk(256);
    proj_kernel<<<dim3(8, 64, 3), blk>>>(queries, keys, values, Wq, Wk, Wv, bq, bk, bv);
    edge_bias_kernel<<<dim3(8, 1024), blk, SMEM_EB>>>(Ek, abias);
    fused_attn_kernel<<<dim3(32, 64), blk, SMEM_FA>>>();
    edgev_kernel<<<1024, blk>>>(Ev);
    final_kernel<<<dim3(8, 64), blk>>>(Wp, bp, out);
}

// round 7
// speedup vs baseline: 1.6098x; 1.1601x over previous
#include <cuda_runtime.h>
#include <cuda_bf16.h>
#include <mma.h>

using namespace nvcuda;

constexpr int B_   = 8;
constexpr int H_   = 8;
constexpr int S_   = 1024;
constexpr int DK_  = 64;
constexpr int EMB_ = 512;
constexpr int HD_  = 512;   // H*DK
constexpr int BH_  = 64;    // B*H
constexpr int SD_  = S_ * DK_;   // 65536
constexpr int SS_  = S_ * S_;    // 1048576
constexpr int TPAD = 1032;       // sT row stride (pad vs 1024)

// Scratch (device globals: allocation-free rule)
__device__ float gQ[BH_ * S_ * DK_];   // tf32-rounded, q pre-scaled by 1/8
__device__ float gK[BH_ * S_ * DK_];   // tf32-rounded
__device__ float gV[BH_ * S_ * DK_];   // tf32-rounded
__device__ float gO[BH_ * S_ * DK_];
__device__ float gS[(size_t)BH_ * S_ * S_];  // 256 MB: score-bias -> weights (tf32)

__device__ __forceinline__ float tf32r(float x) { return wmma::__float_to_tf32(x); }

// ---------------------------------------------------------------------------
// Kernel 1: merged QKV projection, 3xbf16 split. Tile 128x64, k-chunk 32.
// ---------------------------------------------------------------------------
__global__ __launch_bounds__(256)
void proj_kernel(const float* __restrict__ Xq, const float* __restrict__ Xk,
                 const float* __restrict__ Xv,
                 const float* __restrict__ Wq, const float* __restrict__ Wk,
                 const float* __restrict__ Wv,
                 const float* __restrict__ bq, const float* __restrict__ bk,
                 const float* __restrict__ bv)
{
    __shared__ float sBias[16 * 72];
    __shared__ __nv_bfloat16 sAhi[128 * 40], sAlo[128 * 40];
    __shared__ __nv_bfloat16 sBhi[32 * 72],  sBlo[32 * 72];

    const int which = blockIdx.z;
    const float* X    = (which == 0) ? Xq : (which == 1) ? Xk : Xv;
    const float* W    = (which == 0) ? Wq : (which == 1) ? Wk : Wv;
    const float* bias = (which == 0) ? bq : (which == 1) ? bk : bv;
    float* outp       = (which == 0) ? gQ : (which == 1) ? gK : gV;
    const float scale = (which == 0) ? 0.125f : 1.0f;

    const int tid = threadIdx.x;
    const int wid = tid >> 5;
    const int warpRow = wid >> 1;
    const int warpCol = wid & 1;
    const int m0 = blockIdx.y * 128;
    const int n0 = blockIdx.x * 64;
    const int bb = m0 >> 10;
    const int sBase = m0 & 1023;
    const int h  = n0 >> 6;

    #pragma unroll
    for (int i = 0; i < 4; i++) {
        int idx = tid + i * 256;
        int r = idx >> 6, c = idx & 63;
        sBias[r * 72 + c] = bias[n0 + c];
    }
    __syncthreads();

    wmma::fragment<wmma::accumulator, 16, 16, 16, float> acc[2][2];
    #pragma unroll
    for (int mi = 0; mi < 2; mi++)
        #pragma unroll
        for (int ni = 0; ni < 2; ni++)
            wmma::load_matrix_sync(acc[mi][ni], sBias + warpCol * 32 + ni * 16,
                                   72, wmma::mem_row_major);

    for (int kt = 0; kt < 16; kt++) {
        const int k0 = kt * 32;
        #pragma unroll
        for (int i = 0; i < 4; i++) {
            int fi = tid + i * 256;
            int row = fi >> 3, c4 = (fi & 7) * 4;
            float4 v = *(const float4*)(X + (m0 + row) * EMB_ + k0 + c4);
            __nv_bfloat16 hx = __float2bfloat16(v.x), hy = __float2bfloat16(v.y);
            __nv_bfloat16 hz = __float2bfloat16(v.z), hw = __float2bfloat16(v.w);
            __nv_bfloat162 h01(hx, hy), h23(hz, hw);
            __nv_bfloat162 l01(__float2bfloat16(v.x - __bfloat162float(hx)),
                               __float2bfloat16(v.y - __bfloat162float(hy)));
            __nv_bfloat162 l23(__float2bfloat16(v.z - __bfloat162float(hz)),
                               __float2bfloat16(v.w - __bfloat162float(hw)));
            *(__nv_bfloat162*)&sAhi[row * 40 + c4]     = h01;
            *(__nv_bfloat162*)&sAhi[row * 40 + c4 + 2] = h23;
            *(__nv_bfloat162*)&sAlo[row * 40 + c4]     = l01;
            *(__nv_bfloat162*)&sAlo[row * 40 + c4 + 2] = l23;
        }
        #pragma unroll
        for (int i = 0; i < 2; i++) {
            int fi = tid + i * 256;
            int row = fi >> 4, c4 = (fi & 15) * 4;
            float4 v = *(const float4*)(W + (k0 + row) * HD_ + n0 + c4);
            __nv_bfloat16 hx = __float2bfloat16(v.x), hy = __float2bfloat16(v.y);
            __nv_bfloat16 hz = __float2bfloat16(v.z), hw = __float2bfloat16(v.w);
            __nv_bfloat162 h01(hx, hy), h23(hz, hw);
            __nv_bfloat162 l01(__float2bfloat16(v.x - __bfloat162float(hx)),
                               __float2bfloat16(v.y - __bfloat162float(hy)));
            __nv_bfloat162 l23(__float2bfloat16(v.z - __bfloat162float(hz)),
                               __float2bfloat16(v.w - __bfloat162float(hw)));
            *(__nv_bfloat162*)&sBhi[row * 72 + c4]     = h01;
            *(__nv_bfloat162*)&sBhi[row * 72 + c4 + 2] = h23;
            *(__nv_bfloat162*)&sBlo[row * 72 + c4]     = l01;
            *(__nv_bfloat162*)&sBlo[row * 72 + c4 + 2] = l23;
        }
        __syncthreads();
        #pragma unroll
        for (int kk = 0; kk < 2; kk++) {
            wmma::fragment<wmma::matrix_b, 16, 16, 16, __nv_bfloat16, wmma::row_major> bhf[2], blf[2];
            #pragma unroll
            for (int ni = 0; ni < 2; ni++) {
                wmma::load_matrix_sync(bhf[ni], sBhi + (kk * 16) * 72 + warpCol * 32 + ni * 16, 72);
                wmma::load_matrix_sync(blf[ni], sBlo + (kk * 16) * 72 + warpCol * 32 + ni * 16, 72);
            }
            #pragma unroll
            for (int mi = 0; mi < 2; mi++) {
                wmma::fragment<wmma::matrix_a, 16, 16, 16, __nv_bfloat16, wmma::row_major> ah, al;
                wmma::load_matrix_sync(ah, sAhi + (warpRow * 32 + mi * 16) * 40 + kk * 16, 40);
                wmma::load_matrix_sync(al, sAlo + (warpRow * 32 + mi * 16) * 40 + kk * 16, 40);
                #pragma unroll
                for (int ni = 0; ni < 2; ni++) {
                    wmma::mma_sync(acc[mi][ni], ah, bhf[ni], acc[mi][ni]);
                    wmma::mma_sync(acc[mi][ni], ah, blf[ni], acc[mi][ni]);
                    wmma::mma_sync(acc[mi][ni], al, bhf[ni], acc[mi][ni]);
                }
            }
        }
        __syncthreads();
    }

    float* obase = outp + ((bb * H_ + h) << 16);
    #pragma unroll
    for (int mi = 0; mi < 2; mi++)
        #pragma unroll
        for (int ni = 0; ni < 2; ni++) {
            #pragma unroll
            for (int e = 0; e < acc[mi][ni].num_elements; e++)
                acc[mi][ni].x[e] = tf32r(acc[mi][ni].x[e] * scale);
            wmma::store_matrix_sync(
                obase + (sBase + warpRow * 32 + mi * 16) * DK_ + warpCol * 32 + ni * 16,
                acc[mi][ni], DK_, wmma::mem_row_major);
        }
}

// ---------------------------------------------------------------------------
// Kernel 2: gS[bh,q,n] = gQ[bh,q,:]·Ek[q,n,:] + abias[b,q,n].
// n-chunk 64. Ek staged in smem; acc initialized from replicated abias tile;
// result stored directly to gS.
// ---------------------------------------------------------------------------
__global__ __launch_bounds__(256, 4)
void edge_bias_kernel(const float* __restrict__ Ek, const float* __restrict__ abias)
{
    extern __shared__ float dsm[];
    float* sA    = dsm;                  // 64 x 68  (gQ slice: row=bh, col=d)
    float* sEk   = dsm + 64 * 68;        // 64 x 68  (row=n, col=d)
    float* sBias = dsm + 2 * 64 * 68;    // 64 x 72  (abias replicated over h)

    const int tid = threadIdx.x;
    const int wid = tid >> 5;
    const int wr  = wid >> 2;            // 0..1 -> 32 bh rows
    const int wc  = wid & 3;             // 0..3 -> 16 cols
    const int q   = blockIdx.y;
    const int n0  = blockIdx.x * 64;
    const int rowA = tid >> 4;           // 0..15
    const int c4   = (tid & 15) * 4;

    #pragma unroll
    for (int i = 0; i < 4; i++) {
        int row = rowA + i * 16;
        *(float4*)(sA + row * 68 + c4) =
            *(const float4*)(gQ + (size_t)row * SD_ + q * DK_ + c4);
        *(float4*)(sEk + row * 68 + c4) =
            *(const float4*)(Ek + ((size_t)q * S_ + n0 + row) * DK_ + c4);
    }
    #pragma unroll
    for (int i = 0; i < 16; i++) {
        int idx = tid + i * 256;
        int r = idx >> 6, c = idx & 63;
        sBias[r * 72 + c] = abias[(size_t)(r >> 3) * SS_ + (size_t)q * S_ + n0 + c];
    }
    __syncthreads();

    wmma::fragment<wmma::accumulator, 16, 16, 8, float> acc[2];
    #pragma unroll
    for (int mi = 0; mi < 2; mi++)
        wmma::load_matrix_sync(acc[mi], sBias + (wr * 32 + mi * 16) * 72 + wc * 16,
                               72, wmma::mem_row_major);

    #pragma unroll
    for (int kk = 0; kk < 8; kk++) {
        wmma::fragment<wmma::matrix_b, 16, 16, 8, wmma::precision::tf32, wmma::col_major> b;
        wmma::load_matrix_sync(b, sEk + (wc * 16) * 68 + kk * 8, 68);
        #pragma unroll
        for (int mi = 0; mi < 2; mi++) {
            wmma::fragment<wmma::matrix_a, 16, 16, 8, wmma::precision::tf32, wmma::row_major> a;
            wmma::load_matrix_sync(a, sA + (wr * 32 + mi * 16) * 68 + kk * 8, 68);
            wmma::mma_sync(acc[mi], a, b, acc[mi]);
        }
    }

    #pragma unroll
    for (int mi = 0; mi < 2; mi++)
        wmma::store_matrix_sync(
            gS + (size_t)(wr * 32 + mi * 16) * SS_ + (size_t)q * S_ + n0 + wc * 16,
            acc[mi], SS_, wmma::mem_row_major);
}

// ---------------------------------------------------------------------------
// Kernel 3 (FUSED): scores = QK^T + gS -> softmax -> weights (gS, tf32)
//                   -> out = W @ V (gO).  CTA per (bh, 32-q-rows).
// K/V staged through smem with register-prefetch pipeline; sT padded.
// ---------------------------------------------------------------------------
__global__ __launch_bounds__(256, 1)
void fused_attn_kernel()
{
    extern __shared__ float dsm[];
    float* sQ  = dsm;                    // 32 x 72
    float* sKV = dsm + 32 * 72;          // 128 x 68
    float* sT  = dsm + 32 * 72 + 128 * 68;  // 32 x TPAD

    const int tid = threadIdx.x;
    const int wid = tid >> 5;
    const int lane = tid & 31;
    const int bh = blockIdx.y;
    const int q0 = blockIdx.x * 32;
    const int rowA = tid >> 4;           // 0..15
    const int c4   = (tid & 15) * 4;

    #pragma unroll
    for (int i = 0; i < 2; i++) {
        int fi = tid + i * 256;
        int row = fi >> 4, cc = (fi & 15) * 4;
        *(float4*)(sQ + row * 72 + cc) =
            *(const float4*)(gQ + bh * SD_ + (q0 + row) * DK_ + cc);
    }
    __syncthreads();

    // ---- Phase A: scores (K staged, pipelined) ----
    {
        const int wr = wid >> 2;   // 0..1
        const int wc = wid & 3;    // 0..3 -> 32 cols each within 128-chunk
        wmma::fragment<wmma::matrix_a, 16, 16, 8, wmma::precision::tf32, wmma::row_major> a[8];
        #pragma unroll
        for (int kk = 0; kk < 8; kk++)
            wmma::load_matrix_sync(a[kk], sQ + (wr * 16) * 72 + kk * 8, 72);

        const float* Kbase = gK + bh * SD_;
        const float* Sbase = gS + ((size_t)bh * S_ + q0 + wr * 16) * S_;

        float4 pK[8];
        #pragma unroll
        for (int i = 0; i < 8; i++)
            pK[i] = *(const float4*)(Kbase + (rowA + i * 16) * DK_ + c4);

        for (int nc = 0; nc < 8; nc++) {
            __syncthreads();
            #pragma unroll
            for (int i = 0; i < 8; i++)
                *(float4*)(sKV + (rowA + i * 16) * 68 + c4) = pK[i];
            __syncthreads();
            if (nc < 7) {
                const int n1 = (nc + 1) * 128;
                #pragma unroll
                for (int i = 0; i < 8; i++)
                    pK[i] = *(const float4*)(Kbase + (n1 + rowA + i * 16) * DK_ + c4);
            }
            #pragma unroll
            for (int ni = 0; ni < 2; ni++) {
                const int ncol = wc * 32 + ni * 16;
                wmma::fragment<wmma::accumulator, 16, 16, 8, float> acc;
                wmma::load_matrix_sync(acc, Sbase + nc * 128 + ncol, S_, wmma::mem_row_major);
                #pragma unroll
                for (int kk = 0; kk < 8; kk++) {
                    wmma::fragment<wmma::matrix_b, 16, 16, 8, wmma::precision::tf32, wmma::col_major> b;
                    wmma::load_matrix_sync(b, sKV + ncol * 68 + kk * 8, 68);
                    wmma::mma_sync(acc, a[kk], b, acc);
                }
                wmma::store_matrix_sync(sT + (wr * 16) * TPAD + nc * 128 + ncol,
                                        acc, TPAD, wmma::mem_row_major);
            }
        }
    }
    __syncthreads();

    // ---- Phase B: row softmax; tf32 weights to sT and gS ----
    #pragma unroll
    for (int rr = 0; rr < 4; rr++) {
        int r = wid * 4 + rr;
        float* row = sT + r * TPAD;
        float mx = -3.0e38f;
        for (int i = lane; i < 1024; i += 32) mx = fmaxf(mx, row[i]);
        #pragma unroll
        for (int o = 16; o; o >>= 1) mx = fmaxf(mx, __shfl_xor_sync(0xffffffffu, mx, o));
        float sum = 0.0f;
        for (int i = lane; i < 1024; i += 32) {
            float e = expf(row[i] - mx);
            row[i] = e;
            sum += e;
        }
        #pragma unroll
        for (int o = 16; o; o >>= 1) sum += __shfl_xor_sync(0xffffffffu, sum, o);
        float inv = 1.0f / sum;
        float* outr = gS + ((size_t)bh * S_ + q0 + r) * S_;
        for (int i = lane; i < 1024; i += 32) {
            float w = tf32r(row[i] * inv);
            row[i] = w;
            outr[i] = w;
        }
    }

    // ---- Phase C: out = weights @ V (V staged, pipelined) ----
    {
        const int wr = wid >> 2;   // 0..1
        const int wc = wid & 3;    // 0..3 -> 16 cols each
        wmma::fragment<wmma::accumulator, 16, 16, 8, float> c[2];
        wmma::fill_fragment(c[0], 0.0f);
        wmma::fill_fragment(c[1], 0.0f);
        const float* Vbase = gV + bh * SD_;
        const float* Tbase = sT + (wr * 16) * TPAD;

        float4 pV[4];
        #pragma unroll
        for (int i = 0; i < 4; i++)
            pV[i] = *(const float4*)(Vbase + (rowA + i * 16) * DK_ + c4);

        for (int kt = 0; kt < 16; kt++) {
            __syncthreads();
            #pragma unroll
            for (int i = 0; i < 4; i++)
                *(float4*)(sKV + (rowA + i * 16) * 68 + c4) = pV[i];
            __syncthreads();
            if (kt < 15) {
                const int k1 = (kt + 1) * 64;
                #pragma unroll
                for (int i = 0; i < 4; i++)
                    pV[i] = *(const float4*)(Vbase + (k1 + rowA + i * 16) * DK_ + c4);
            }
            #pragma unroll
            for (int kk = 0; kk < 8; kk++) {
                wmma::fragment<wmma::matrix_a, 16, 16, 8, wmma::precision::tf32, wmma::row_major> a;
                wmma::fragment<wmma::matrix_b, 16, 16, 8, wmma::precision::tf32, wmma::row_major> b;
                wmma::load_matrix_sync(a, Tbase + kt * 64 + kk * 8, TPAD);
                wmma::load_matrix_sync(b, sKV + (kk * 8) * 68 + wc * 16, 68);
                wmma::mma_sync(c[kk & 1], a, b, c[kk & 1]);
            }
        }
        #pragma unroll
        for (int e = 0; e < c[0].num_elements; e++) c[0].x[e] += c[1].x[e];
        wmma::store_matrix_sync(gO + bh * SD_ + (q0 + wr * 16) * DK_ + wc * 16,
                                c[0], DK_, wmma::mem_row_major);
    }
}

// ---------------------------------------------------------------------------
// Kernel 4: gO += weights[:,q,:] @ Ev[q]. Staged smem + register prefetch.
// ---------------------------------------------------------------------------
__global__ __launch_bounds__(256, 4)
void edgev_kernel(const float* __restrict__ Ev)
{
    __shared__ float sA[64 * 68];
    __shared__ float sB[64 * 68];

    const int tid = threadIdx.x;
    const int wid = tid >> 5;
    const int warpRow = wid >> 1;   // 0..3 -> 16 bh rows
    const int warpCol = wid & 1;    // 0..1 -> 32 cols
    const int q = blockIdx.x;
    const int rowA = tid >> 4;      // 0..15
    const int c4   = (tid & 15) * 4;

    wmma::fragment<wmma::accumulator, 16, 16, 8, float> acc[2];
    #pragma unroll
    for (int j = 0; j < 2; j++)
        wmma::load_matrix_sync(acc[j],
            gO + (size_t)(warpRow * 16) * SD_ + q * DK_ + warpCol * 32 + j * 16,
            SD_, wmma::mem_row_major);

    float4 pA[4], pB[4];
    #pragma unroll
    for (int i = 0; i < 4; i++) {
        int row = rowA + i * 16;
        pA[i] = *(const float4*)(gS + (size_t)row * SS_ + (size_t)q * S_ + c4);
        pB[i] = *(const float4*)(Ev + ((size_t)q * S_ + row) * DK_ + c4);
    }

    for (int kt = 0; kt < 16; kt++) {
        __syncthreads();
        #pragma unroll
        for (int i = 0; i < 4; i++) {
            int row = rowA + i * 16;
            *(float4*)(sA + row * 68 + c4) = pA[i];
            *(float4*)(sB + row * 68 + c4) = pB[i];
        }
        __syncthreads();
        if (kt < 15) {
            const int k1 = (kt + 1) * 64;
            #pragma unroll
            for (int i = 0; i < 4; i++) {
                int row = rowA + i * 16;
                pA[i] = *(const float4*)(gS + (size_t)row * SS_ + (size_t)q * S_ + k1 + c4);
                pB[i] = *(const float4*)(Ev + ((size_t)q * S_ + k1 + row) * DK_ + c4);
            }
        }
        #pragma unroll
        for (int kk = 0; kk < 8; kk++) {
            wmma::fragment<wmma::matrix_a, 16, 16, 8, wmma::precision::tf32, wmma::row_major> a;
            wmma::load_matrix_sync(a, sA + (warpRow * 16) * 68 + kk * 8, 68);
            #pragma unroll
            for (int j = 0; j < 2; j++) {
                wmma::fragment<wmma::matrix_b, 16, 16, 8, wmma::precision::tf32, wmma::row_major> b;
                wmma::load_matrix_sync(b, sB + (kk * 8) * 68 + warpCol * 32 + j * 16, 68);
                wmma::mma_sync(acc[j], a, b, acc[j]);
            }
        }
    }

    #pragma unroll
    for (int j = 0; j < 2; j++)
        wmma::store_matrix_sync(
            gO + (size_t)(warpRow * 16) * SD_ + q * DK_ + warpCol * 32 + j * 16,
            acc[j], SD_, wmma::mem_row_major);
}

// ---------------------------------------------------------------------------
// Kernel 5: out = concat_heads(gO) @ Wp + bp. 3xbf16 split, tile 128x64.
// ---------------------------------------------------------------------------
__global__ __launch_bounds__(256)
void final_kernel(const float* __restrict__ Wp, const float* __restrict__ bp,
                  float* __restrict__ out)
{
    __shared__ float sBias[16 * 72];
    __shared__ __nv_bfloat16 sAhi[128 * 40], sAlo[128 * 40];
    __shared__ __nv_bfloat16 sBhi[32 * 72],  sBlo[32 * 72];

    const int tid = threadIdx.x;
    const int wid = tid >> 5;
    const int warpRow = wid >> 1;
    const int warpCol = wid & 1;
    const int m0 = blockIdx.y * 128;
    const int n0 = blockIdx.x * 64;
    const int bb = m0 >> 10;
    const int sBase = m0 & 1023;

    #pragma unroll
    for (int i = 0; i < 4; i++) {
        int idx = tid + i * 256;
        int r = idx >> 6, c = idx & 63;
        sBias[r * 72 + c] = bp[n0 + c];
    }
    __syncthreads();

    wmma::fragment<wmma::accumulator, 16, 16, 16, float> acc[2][2];
    #pragma unroll
    for (int mi = 0; mi < 2; mi++)
        #pragma unroll
        for (int ni = 0; ni < 2; ni++)
            wmma::load_matrix_sync(acc[mi][ni], sBias + warpCol * 32 + ni * 16,
                                   72, wmma::mem_row_major);

    for (int kt = 0; kt < 16; kt++) {
        const int k0 = kt * 32;
        const int h = k0 >> 6, d0 = k0 & 63;
        const float* Abase = gO + ((bb * H_ + h) << 16) + d0;
        #pragma unroll
        for (int i = 0; i < 4; i++) {
            int fi = tid + i * 256;
            int row = fi >> 3, c4 = (fi & 7) * 4;
            float4 v = *(const float4*)(Abase + (sBase + row) * DK_ + c4);
            __nv_bfloat16 hx = __float2bfloat16(v.x), hy = __float2bfloat16(v.y);
            __nv_bfloat16 hz = __float2bfloat16(v.z), hw = __float2bfloat16(v.w);
            __nv_bfloat162 h01(hx, hy), h23(hz, hw);
            __nv_bfloat162 l01(__float2bfloat16(v.x - __bfloat162float(hx)),
                               __float2bfloat16(v.y - __bfloat162float(hy)));
            __nv_bfloat162 l23(__float2bfloat16(v.z - __bfloat162float(hz)),
                               __float2bfloat16(v.w - __bfloat162float(hw)));
            *(__nv_bfloat162*)&sAhi[row * 40 + c4]     = h01;
            *(__nv_bfloat162*)&sAhi[row * 40 + c4 + 2] = h23;
            *(__nv_bfloat162*)&sAlo[row * 40 + c4]     = l01;
            *(__nv_bfloat162*)&sAlo[row * 40 + c4 + 2] = l23;
        }
        #pragma unroll
        for (int i = 0; i < 2; i++) {
            int fi = tid + i * 256;
            int row = fi >> 4, c4 = (fi & 15) * 4;
            float4 v = *(const float4*)(Wp + (k0 + row) * HD_ + n0 + c4);
            __nv_bfloat16 hx = __float2bfloat16(v.x), hy = __float2bfloat16(v.y);
            __nv_bfloat16 hz = __float2bfloat16(v.z), hw = __float2bfloat16(v.w);
            __nv_bfloat162 h01(hx, hy), h23(hz, hw);
            __nv_bfloat162 l01(__float2bfloat16(v.x - __bfloat162float(hx)),
                               __float2bfloat16(v.y - __bfloat162float(hy)));
            __nv_bfloat162 l23(__float2bfloat16(v.z - __bfloat162float(hz)),
                               __float2bfloat16(v.w - __bfloat162float(hw)));
            *(__nv_bfloat162*)&sBhi[row * 72 + c4]     = h01;
            *(__nv_bfloat162*)&sBhi[row * 72 + c4 + 2] = h23;
            *(__nv_bfloat162*)&sBlo[row * 72 + c4]     = l01;
            *(__nv_bfloat162*)&sBlo[row * 72 + c4 + 2] = l23;
        }
        __syncthreads();
        #pragma unroll
        for (int kk = 0; kk < 2; kk++) {
            wmma::fragment<wmma::matrix_b, 16, 16, 16, __nv_bfloat16, wmma::row_major> bhf[2], blf[2];
            #pragma unroll
            for (int ni = 0; ni < 2; ni++) {
                wmma::load_matrix_sync(bhf[ni], sBhi + (kk * 16) * 72 + warpCol * 32 + ni * 16, 72);
                wmma::load_matrix_sync(blf[ni], sBlo + (kk * 16) * 72 + warpCol * 32 + ni * 16, 72);
            }
            #pragma unroll
            for (int mi = 0; mi < 2; mi++) {
                wmma::fragment<wmma::matrix_a, 16, 16, 16, __nv_bfloat16, wmma::row_major> ah, al;
                wmma::load_matrix_sync(ah, sAhi + (warpRow * 32 + mi * 16) * 40 + kk * 16, 40);
                wmma::load_matrix_sync(al, sAlo + (warpRow * 32 + mi * 16) * 40 + kk * 16, 40);
                #pragma unroll
                for (int ni = 0; ni < 2; ni++) {
                    wmma::mma_sync(acc[mi][ni], ah, bhf[ni], acc[mi][ni]);
                    wmma::mma_sync(acc[mi][ni], ah, blf[ni], acc[mi][ni]);
                    wmma::mma_sync(acc[mi][ni], al, bhf[ni], acc[mi][ni]);
                }
            }
        }
        __syncthreads();
    }

    #pragma unroll
    for (int mi = 0; mi < 2; mi++)
        #pragma unroll
        for (int ni = 0; ni < 2; ni++)
            wmma::store_matrix_sync(
                out + (m0 + warpRow * 32 + mi * 16) * HD_ + n0 + warpCol * 32 + ni * 16,
                acc[mi][ni], HD_, wmma::mem_row_major);
}

// ---------------------------------------------------------------------------
extern "C" void kernel_launch(void* const* d_in, const int* in_sizes, int n_in,
                              void* d_out, int out_size)
{
    const float* queries = (const float*)d_in[0];
    const float* keys    = (const float*)d_in[1];
    const float* values  = (const float*)d_in[2];
    const float* Ek      = (const float*)d_in[3];
    const float* Ev      = (const float*)d_in[4];
    const float* abias   = (const float*)d_in[5];
    const float* Wq = (const float*)d_in[6];
    const float* bq = (const float*)d_in[7];
    const float* Wk = (const float*)d_in[8];
    const float* bk = (const float*)d_in[9];
    const float* Wv = (const float*)d_in[10];
    const float* bv = (const float*)d_in[11];
    const float* Wp = (const float*)d_in[12];
    const float* bp = (const float*)d_in[13];
    float* out = (float*)d_out;

    const int SMEM_EB = (2 * 64 * 68 + 64 * 72) * (int)sizeof(float);           // 53248
    const int SMEM_FA = (32 * 72 + 128 * 68 + 32 * TPAD) * (int)sizeof(float);  // 176128
    cudaFuncSetAttribute(edge_bias_kernel, cudaFuncAttributeMaxDynamicSharedMemorySize, SMEM_EB);
    cudaFuncSetAttribute(fused_attn_kernel, cudaFuncAttributeMaxDynamicSharedMemorySize, SMEM_FA);

    dim3 blk(256);
    proj_kernel<<<dim3(8, 64, 3), blk>>>(queries, keys, values, Wq, Wk, Wv, bq, bk, bv);
    edge_bias_kernel<<<dim3(16, 1024), blk, SMEM_EB>>>(Ek, abias);
    fused_attn_kernel<<<dim3(32, 64), blk, SMEM_FA>>>();
    edgev_kernel<<<1024, blk>>>(Ev);
    final_kernel<<<dim3(8, 64), blk>>>(Wp, bp, out);
}